// round 6
// baseline (speedup 1.0000x reference)
#include <cuda_runtime.h>
#include <cuda_bf16.h>
#include <math.h>
#include <stdint.h>

#define NPOS 16384          // H*W
#define NB   16             // batch
#define NCH  128            // C == hidden

// ---------------- device scratch (allocation-free rule: __device__ globals) ----
__device__ uint32_t g_qhi [NB * NPOS * 64];      // q bf16-hi pairs    [b][n][ch/2]
__device__ uint32_t g_qlo [NB * NPOS * 64];      // q bf16-lo pairs
__device__ uint32_t g_ekhi[NB * NPOS * 64];      // exp(k) bf16-hi     [b][n][ch/2]
__device__ uint32_t g_eklo[NB * NPOS * 64];
__device__ uint32_t g_vhi [NB * NPOS * 64];      // v bf16-hi          [b][n][ch/2]
__device__ uint32_t g_vlo [NB * NPOS * 64];
__device__ float    g_part[NB * 128 * 4224];     // per (b,nchunk): 4x1024 ctx + 128 sumexp
__device__ float    g_ctx [NB * 4224];           // reduced
__device__ uint32_t g_W2hi[NB * NCH * 64];       // fused W2 bf16-hi   [b][c][ch/2]
__device__ uint32_t g_W2lo[NB * NCH * 64];

// ---------------- helpers -------------------------------------------------------
__device__ __forceinline__ uint32_t smem_u32(const void* p) {
    uint32_t a;
    asm("{ .reg .u64 t; cvta.to.shared.u64 t, %1; cvt.u32.u64 %0, t; }" : "=r"(a) : "l"(p));
    return a;
}
// swizzled byte offset within a 128-col bf16 tile (256B rows, XOR on 16B chunks)
__device__ __forceinline__ uint32_t toff(int r, int c) {
    return (uint32_t)(r * 256 + (((c >> 3) ^ (r & 7)) << 4) + ((c & 7) << 1));
}
__device__ __forceinline__ void ldsm4(uint32_t* r, uint32_t a) {
    asm volatile("ldmatrix.sync.aligned.m8n8.x4.shared.b16 {%0,%1,%2,%3}, [%4];"
                 : "=r"(r[0]), "=r"(r[1]), "=r"(r[2]), "=r"(r[3]) : "r"(a));
}
__device__ __forceinline__ void ldsm4t(uint32_t* r, uint32_t a) {
    asm volatile("ldmatrix.sync.aligned.m8n8.x4.trans.shared.b16 {%0,%1,%2,%3}, [%4];"
                 : "=r"(r[0]), "=r"(r[1]), "=r"(r[2]), "=r"(r[3]) : "r"(a));
}
__device__ __forceinline__ void mma16816(float* d, const uint32_t* a, uint32_t b0, uint32_t b1) {
    asm volatile(
        "mma.sync.aligned.m16n8k16.row.col.f32.bf16.bf16.f32 "
        "{%0,%1,%2,%3}, {%4,%5,%6,%7}, {%8,%9}, {%0,%1,%2,%3};"
        : "+f"(d[0]), "+f"(d[1]), "+f"(d[2]), "+f"(d[3])
        : "r"(a[0]), "r"(a[1]), "r"(a[2]), "r"(a[3]), "r"(b0), "r"(b1));
}
__device__ __forceinline__ void split_pair(float v0, float v1, uint32_t& hi, uint32_t& lo) {
    __nv_bfloat162 h = __float22bfloat162_rn(make_float2(v0, v1));
    float2 hf = __bfloat1622float2(h);
    __nv_bfloat162 l = __float22bfloat162_rn(make_float2(v0 - hf.x, v1 - hf.y));
    hi = *(uint32_t*)&h;
    lo = *(uint32_t*)&l;
}

// 128x128x128 warp-tiled GEMM pass (as R5, verified).
template<bool ATRANS>
__device__ __forceinline__ void gemm128(float (&acc)[2][8][4], uint32_t aB, uint32_t bB,
                                        int wm, int wn, int lane)
{
    const int l7  = lane & 7;
    const int lb3 = (lane >> 3) & 1;
    const int lb4 = (lane >> 4) & 1;
#pragma unroll
    for (int k = 0; k < 8; k++) {
        uint32_t a[2][4];
#pragma unroll
        for (int t = 0; t < 2; t++) {
            uint32_t addr;
            if (ATRANS)
                addr = aB + toff(k * 16 + l7 + lb4 * 8, wm * 32 + t * 16 + lb3 * 8);
            else
                addr = aB + toff(wm * 32 + t * 16 + l7 + lb3 * 8, k * 16 + lb4 * 8);
            if (ATRANS) ldsm4t(a[t], addr); else ldsm4(a[t], addr);
        }
        uint32_t bf[4][4];
#pragma unroll
        for (int u2 = 0; u2 < 4; u2++)
            ldsm4(bf[u2], bB + toff(wn * 64 + u2 * 16 + l7 + lb4 * 8, k * 16 + lb3 * 8));
#pragma unroll
        for (int t = 0; t < 2; t++)
#pragma unroll
            for (int u = 0; u < 8; u++)
                mma16816(acc[t][u], a[t], bf[u >> 1][(u & 1) * 2], bf[u >> 1][(u & 1) * 2 + 1]);
    }
}

// load a 128x128 f32 tile (row stride strideF) into split bf16 hi/lo swizzled tiles
__device__ __forceinline__ void load_split(char* smc, int hiOff, int loOff,
                                           const float* __restrict__ src,
                                           int strideF, int tid)
{
#pragma unroll
    for (int i = 0; i < 16; i++) {
        int lin = tid + i * 256;
        int r = lin >> 5, cq = lin & 31;
        float4 v = *(const float4*)(src + (size_t)r * strideF + cq * 4);
        uint32_t h01, l01, h23, l23;
        split_pair(v.x, v.y, h01, l01);
        split_pair(v.z, v.w, h23, l23);
        uint32_t o = toff(r, cq * 4);
        *(uint32_t*)(smc + hiOff + o)     = h01;
        *(uint32_t*)(smc + hiOff + o + 4) = h23;
        *(uint32_t*)(smc + loOff + o)     = l01;
        *(uint32_t*)(smc + loOff + o + 4) = l23;
    }
}

// =============================================================================
// K1: qkv = w_qkv @ x via mma.sync bf16-split.  Fused q-softmax; k-chunk stores
// exp(k), v-chunk stores v, both as split-bf16 pairs [b][n][ch/2].
// smem: xs hi/lo 64K | ws hi/lo 64K = 131072 B
// =============================================================================
#define K1_XHI 0
#define K1_XLO 32768
#define K1_WHI 65536
#define K1_WLO 98304

__global__ __launch_bounds__(256, 1)
void k_qkv(const float* __restrict__ x, const float* __restrict__ w_qkv)
{
    extern __shared__ char smc[];
    const uint32_t sb = smem_u32(smc);
    const int tid = threadIdx.x;
    const int warp = tid >> 5, lane = tid & 31;
    const int wm = warp & 3, wn = warp >> 2;

    const int b  = blockIdx.x >> 7;
    const int n0 = (blockIdx.x & 127) << 7;

    load_split(smc, K1_XHI, K1_XLO, x + (size_t)b * NCH * NPOS + n0, NPOS, tid);
    load_split(smc, K1_WHI, K1_WLO, w_qkv, NCH, tid);
    __syncthreads();

    for (int chunk = 0; chunk < 3; chunk++) {
        float acc[2][8][4];
#pragma unroll
        for (int t = 0; t < 2; t++)
#pragma unroll
            for (int u = 0; u < 8; u++)
#pragma unroll
                for (int r = 0; r < 4; r++) acc[t][u][r] = 0.f;

        gemm128<true>(acc, sb + K1_XHI, sb + K1_WHI, wm, wn, lane);
        gemm128<true>(acc, sb + K1_XHI, sb + K1_WLO, wm, wn, lane);
        gemm128<true>(acc, sb + K1_XLO, sb + K1_WHI, wm, wn, lane);

        if (chunk == 0) {
            // q: softmax over 32 channels per head
            const float scale = 0.17677669529663687f; // 32^-0.5
#pragma unroll
            for (int t = 0; t < 2; t++)
#pragma unroll
            for (int rh = 0; rh < 2; rh++) {
                float e[8][2];
                float sA = 0.f, sB = 0.f;
#pragma unroll
                for (int u = 0; u < 8; u++)
#pragma unroll
                    for (int j = 0; j < 2; j++) {
                        float v = __expf(acc[t][u][rh * 2 + j]);
                        e[u][j] = v;
                        if (u < 4) sA += v; else sB += v;
                    }
                sA += __shfl_xor_sync(0xffffffffu, sA, 1);
                sA += __shfl_xor_sync(0xffffffffu, sA, 2);
                sB += __shfl_xor_sync(0xffffffffu, sB, 1);
                sB += __shfl_xor_sync(0xffffffffu, sB, 2);
                const float invA = scale / sA, invB = scale / sB;
                const int p = wm * 32 + t * 16 + rh * 8 + (lane >> 2);
                const size_t rowb = ((size_t)b * NPOS + n0 + p) * 64;
#pragma unroll
                for (int u = 0; u < 8; u++) {
                    float inv = (u < 4) ? invA : invB;
                    uint32_t hi, lo;
                    split_pair(e[u][0] * inv, e[u][1] * inv, hi, lo);
                    int cp = wn * 32 + u * 4 + (lane & 3);
                    g_qhi[rowb + cp] = hi;
                    g_qlo[rowb + cp] = lo;
                }
            }
        } else {
            uint32_t* ghi = (chunk == 1) ? g_ekhi : g_vhi;
            uint32_t* glo = (chunk == 1) ? g_eklo : g_vlo;
#pragma unroll
            for (int t = 0; t < 2; t++)
#pragma unroll
            for (int rh = 0; rh < 2; rh++) {
                const int p = wm * 32 + t * 16 + rh * 8 + (lane >> 2);
                const size_t rowb = ((size_t)b * NPOS + n0 + p) * 64;
#pragma unroll
                for (int u = 0; u < 8; u++) {
                    float v0 = acc[t][u][rh * 2], v1 = acc[t][u][rh * 2 + 1];
                    if (chunk == 1) { v0 = __expf(v0); v1 = __expf(v1); }
                    uint32_t hi, lo;
                    split_pair(v0, v1, hi, lo);
                    int cp = wn * 32 + u * 4 + (lane & 3);
                    ghi[rowb + cp] = hi;
                    glo[rowb + cp] = lo;
                }
            }
        }

        __syncthreads();
        if (chunk < 2) {
            load_split(smc, K1_WHI, K1_WLO, w_qkv + (size_t)(chunk + 1) * 128 * NCH, NCH, tid);
            __syncthreads();
        }
    }
}

// =============================================================================
// K2a: block = (b, 128-n chunk).  All 4 heads: ctx_h[d][e] += sum_p ek[p,d]v[p,e]
// via trans-ldmatrix mma.sync (3 split passes); sumexp folded into the loads.
// smem: ek hi/lo 64K | v hi/lo 64K | red 32K | se 2K = 165,888 B
// =============================================================================
#define C_EKHI 0
#define C_EKLO 32768
#define C_VHI  65536
#define C_VLO  98304
#define C_RED  131072
#define C_SE   163840

__global__ __launch_bounds__(256, 1)
void k_ctx()
{
    extern __shared__ char smc[];
    const uint32_t sb = smem_u32(smc);
    const int tid = threadIdx.x;
    const int warp = tid >> 5, lane = tid & 31;
    const int b  = blockIdx.x >> 7;
    const int ck = blockIdx.x & 127;
    const size_t rowbase = ((size_t)b * NPOS + (size_t)ck * 128) * 64;

    const int cp = tid & 63;        // fixed channel-pair per thread
    float s0 = 0.f, s1 = 0.f;
#pragma unroll
    for (int i = 0; i < 32; i++) {
        int r = (tid >> 6) + i * 4;
        uint32_t u = g_ekhi[rowbase + (size_t)r * 64 + cp];
        *(uint32_t*)(smc + C_EKHI + toff(r, cp * 2)) = u;
        float2 f = __bfloat1622float2(*(__nv_bfloat162*)&u);
        s0 += f.x; s1 += f.y;
    }
#pragma unroll
    for (int i = 0; i < 32; i++) {
        int r = (tid >> 6) + i * 4;
        uint32_t u = g_eklo[rowbase + (size_t)r * 64 + cp];
        *(uint32_t*)(smc + C_EKLO + toff(r, cp * 2)) = u;
        float2 f = __bfloat1622float2(*(__nv_bfloat162*)&u);
        s0 += f.x; s1 += f.y;
    }
#pragma unroll
    for (int i = 0; i < 32; i++) {
        int r = (tid >> 6) + i * 4;
        *(uint32_t*)(smc + C_VHI + toff(r, cp * 2)) = g_vhi[rowbase + (size_t)r * 64 + cp];
        *(uint32_t*)(smc + C_VLO + toff(r, cp * 2)) = g_vlo[rowbase + (size_t)r * 64 + cp];
    }
    {
        float* se = (float*)(smc + C_SE);
        se[(tid >> 6) * 128 + cp * 2]     = s0;
        se[(tid >> 6) * 128 + cp * 2 + 1] = s1;
    }
    __syncthreads();

    const int h = warp & 3, ks = warp >> 2;
    const int l7 = lane & 7, lb3 = (lane >> 3) & 1, lb4 = (lane >> 4) & 1;

    float acc[2][4][4];
#pragma unroll
    for (int mt = 0; mt < 2; mt++)
#pragma unroll
        for (int u = 0; u < 4; u++)
#pragma unroll
            for (int r = 0; r < 4; r++) acc[mt][u][r] = 0.f;

    const int PA[3] = {C_EKHI, C_EKHI, C_EKLO};
    const int PB[3] = {C_VHI,  C_VLO,  C_VHI};
#pragma unroll
    for (int ps = 0; ps < 3; ps++) {
        const uint32_t aB = sb + PA[ps], bB = sb + PB[ps];
#pragma unroll
        for (int kk = 0; kk < 4; kk++) {
            const int p0 = ks * 64 + kk * 16;
            uint32_t a[2][4];
#pragma unroll
            for (int mt = 0; mt < 2; mt++)
                ldsm4t(a[mt], aB + toff(p0 + l7 + lb4 * 8, h * 32 + mt * 16 + lb3 * 8));
            uint32_t bfr[2][4];
#pragma unroll
            for (int nt = 0; nt < 2; nt++)
                ldsm4t(bfr[nt], bB + toff(p0 + l7 + lb3 * 8, h * 32 + nt * 16 + lb4 * 8));
#pragma unroll
            for (int mt = 0; mt < 2; mt++)
#pragma unroll
                for (int u = 0; u < 4; u++)
                    mma16816(acc[mt][u], a[mt], bfr[u >> 1][(u & 1) * 2], bfr[u >> 1][(u & 1) * 2 + 1]);
        }
    }

    // stage per-warp ctx fragments, combine the 2 k-slices
    {
        float* rb = (float*)(smc + C_RED) + ks * 4096 + h * 1024;
#pragma unroll
        for (int mt = 0; mt < 2; mt++)
#pragma unroll
            for (int u = 0; u < 4; u++) {
                int dr = mt * 16 + (lane >> 2), e = u * 8 + (lane & 3) * 2;
                rb[dr * 32 + e]           = acc[mt][u][0];
                rb[dr * 32 + e + 1]       = acc[mt][u][1];
                rb[(dr + 8) * 32 + e]     = acc[mt][u][2];
                rb[(dr + 8) * 32 + e + 1] = acc[mt][u][3];
            }
    }
    __syncthreads();

    const size_t pbase = (size_t)blockIdx.x * 4224;
    const float* r0 = (const float*)(smc + C_RED);
    for (int idx = tid; idx < 4096; idx += 256)
        g_part[pbase + idx] = r0[idx] + r0[4096 + idx];
    if (tid < 128) {
        const float* se = (const float*)(smc + C_SE);
        g_part[pbase + 4096 + tid] = se[tid] + se[128 + tid] + se[256 + tid] + se[384 + tid];
    }
}

// =============================================================================
// K2b-1: reduce 128 chunk partials -> g_ctx[b][4224]
// =============================================================================
__global__ __launch_bounds__(128, 8)
void k_red()
{
    const int b = blockIdx.x / 33, sc = blockIdx.x % 33;
    const int slot = sc * 128 + threadIdx.x;
    const float* src = g_part + (size_t)b * 128 * 4224 + slot;
    float s = 0.f;
#pragma unroll 4
    for (int ckk = 0; ckk < 128; ckk++) s += src[(size_t)ckk * 4224];
    g_ctx[b * 4224 + slot] = s;
}

// =============================================================================
// K2b-2: normalize ctx by sumexp, build fused W2 = w_out x ctx_norm, split bf16
// smem: ctxs 4224 | Ss 128 | ws2 16384 floats = 82,944 B
// =============================================================================
__global__ __launch_bounds__(256, 1)
void k_w2(const float* __restrict__ w_out)
{
    extern __shared__ float sm[];
    float* ctxs = sm;            // [h][d][33]
    float* Ss   = sm + 4224;
    float* ws2  = sm + 4352;     // [c][ch]

    const int b = blockIdx.x;
    const int tid = threadIdx.x;

    for (int lin = tid; lin < 16384; lin += 256) ws2[lin] = w_out[lin];
    for (int idx = tid; idx < 4096; idx += 256) {
        int h = idx >> 10, de = idx & 1023;
        ctxs[h * 1056 + (de >> 5) * 33 + (de & 31)] = g_ctx[b * 4224 + idx];
    }
    if (tid < 128) Ss[tid] = 1.0f / g_ctx[b * 4224 + 4096 + tid];
    __syncthreads();

    for (int oidx = tid; oidx < 8192; oidx += 256) {
        int c = oidx >> 6, cpp = oidx & 63;
        int ch0 = cpp * 2;
        int h = ch0 >> 5, d = ch0 & 31;
        const float* cr0 = &ctxs[h * 1056 + d * 33];
        const float* cr1 = cr0 + 33;
        const float* wr  = &ws2[c * 128 + h * 32];
        float a0 = 0.f, a1 = 0.f;
#pragma unroll
        for (int e = 0; e < 32; e++) {
            a0 = fmaf(wr[e], cr0[e], a0);
            a1 = fmaf(wr[e], cr1[e], a1);
        }
        uint32_t hi, lo;
        split_pair(a0 * Ss[ch0], a1 * Ss[ch0 + 1], hi, lo);
        g_W2hi[(size_t)b * 8192 + oidx] = hi;
        g_W2lo[(size_t)b * 8192 + oidx] = lo;
    }
}

// =============================================================================
// K3: y = W2_b @ q + b_out via mma.sync bf16-split, LayerNorm over C fused.
// 64 positions per block -> 2 CTAs/SM.  M=128 c, N=64 p.
// smem: W2 hi/lo 64K | q hi/lo 32K | red 2K | stats 0.5K = 100,864 B
// =============================================================================
#define K3_WHI 0
#define K3_WLO 32768
#define K3_QHI 65536
#define K3_QLO 81920
#define K3_RS  98304
#define K3_RQ  99328
#define K3_MU  100352
#define K3_RST 100608

__global__ __launch_bounds__(256, 2)
void k_out(const float* __restrict__ b_out, const float* __restrict__ ln_g,
           const float* __restrict__ ln_b, float* __restrict__ out)
{
    extern __shared__ char smc[];
    const uint32_t sb = smem_u32(smc);
    float* red_s = (float*)(smc + K3_RS);    // [4][64]
    float* red_q = (float*)(smc + K3_RQ);    // [4][64]
    float* mu_s  = (float*)(smc + K3_MU);    // [64]
    float* rs_s  = (float*)(smc + K3_RST);   // [64]

    const int tid = threadIdx.x;
    const int warp = tid >> 5, lane = tid & 31;
    const int wm = warp & 3, wn = warp >> 2;          // wn in {0,1}
    const int b  = blockIdx.x >> 8;
    const int n0 = (blockIdx.x & 255) << 6;

#pragma unroll
    for (int i = 0; i < 32; i++) {
        int it = tid + i * 256;              // 8192: W2 tile [c][ch]
        int r = it >> 6, cpp = it & 63;
        uint32_t o = toff(r, cpp * 2);
        *(uint32_t*)(smc + K3_WHI + o) = g_W2hi[(size_t)b * 8192 + it];
        *(uint32_t*)(smc + K3_WLO + o) = g_W2lo[(size_t)b * 8192 + it];
    }
#pragma unroll
    for (int i = 0; i < 16; i++) {
        int it = tid + i * 256;              // 4096: q tile [p<64][ch]
        int r = it >> 6, cpp = it & 63;
        uint32_t o = toff(r, cpp * 2);
        size_t src = ((size_t)b * NPOS + n0 + r) * 64 + cpp;
        *(uint32_t*)(smc + K3_QHI + o) = g_qhi[src];
        *(uint32_t*)(smc + K3_QLO + o) = g_qlo[src];
    }
    __syncthreads();

    const int l7 = lane & 7, lb3 = (lane >> 3) & 1, lb4 = (lane >> 4) & 1;
    float acc[2][4][4];
#pragma unroll
    for (int mt = 0; mt < 2; mt++)
#pragma unroll
        for (int u = 0; u < 4; u++)
#pragma unroll
            for (int r = 0; r < 4; r++) acc[mt][u][r] = 0.f;

    const int PA[3] = {K3_WHI, K3_WHI, K3_WLO};
    const int PB[3] = {K3_QHI, K3_QLO, K3_QHI};
#pragma unroll
    for (int ps = 0; ps < 3; ps++) {
        const uint32_t aB = sb + PA[ps], bB = sb + PB[ps];
#pragma unroll
        for (int k = 0; k < 8; k++) {
            uint32_t a[2][4];
#pragma unroll
            for (int mt = 0; mt < 2; mt++)
                ldsm4(a[mt], aB + toff(wm * 32 + mt * 16 + l7 + lb3 * 8, k * 16 + lb4 * 8));
            uint32_t bfr[2][4];
#pragma unroll
            for (int nt = 0; nt < 2; nt++)
                ldsm4(bfr[nt], bB + toff(wn * 32 + nt * 16 + l7 + lb4 * 8, k * 16 + lb3 * 8));
#pragma unroll
            for (int mt = 0; mt < 2; mt++)
#pragma unroll
                for (int u = 0; u < 4; u++)
                    mma16816(acc[mt][u], a[mt], bfr[u >> 1][(u & 1) * 2], bfr[u >> 1][(u & 1) * 2 + 1]);
        }
    }

    // bias
#pragma unroll
    for (int mt = 0; mt < 2; mt++)
#pragma unroll
        for (int h8 = 0; h8 < 2; h8++) {
            const float bo = b_out[wm * 32 + mt * 16 + h8 * 8 + (lane >> 2)];
#pragma unroll
            for (int u = 0; u < 4; u++) {
                acc[mt][u][h8 * 2]     += bo;
                acc[mt][u][h8 * 2 + 1] += bo;
            }
        }

    // LN partials: column sums over this warp's 32 c-rows
#pragma unroll
    for (int u = 0; u < 4; u++)
#pragma unroll
        for (int j = 0; j < 2; j++) {
            float a0 = acc[0][u][j],     a1 = acc[0][u][2 + j];
            float a2 = acc[1][u][j],     a3 = acc[1][u][2 + j];
            float s = a0 + a1 + a2 + a3;
            float q = a0 * a0 + a1 * a1 + a2 * a2 + a3 * a3;
            s += __shfl_xor_sync(0xffffffffu, s, 4);
            q += __shfl_xor_sync(0xffffffffu, q, 4);
            s += __shfl_xor_sync(0xffffffffu, s, 8);
            q += __shfl_xor_sync(0xffffffffu, q, 8);
            s += __shfl_xor_sync(0xffffffffu, s, 16);
            q += __shfl_xor_sync(0xffffffffu, q, 16);
            if ((lane >> 2) == 0) {
                int col = wn * 32 + u * 8 + (lane & 3) * 2 + j;
                red_s[wm * 64 + col] = s;
                red_q[wm * 64 + col] = q;
            }
        }
    __syncthreads();

    if (tid < 64) {
        float s = red_s[tid] + red_s[64 + tid] + red_s[128 + tid] + red_s[192 + tid];
        float q = red_q[tid] + red_q[64 + tid] + red_q[128 + tid] + red_q[192 + tid];
        float mu  = s * (1.0f / 128.0f);
        float var = q * (1.0f / 128.0f) - mu * mu;
        mu_s[tid] = mu;
        rs_s[tid] = rsqrtf(var + 1e-5f);
    }
    __syncthreads();

#pragma unroll
    for (int mt = 0; mt < 2; mt++)
#pragma unroll
        for (int h8 = 0; h8 < 2; h8++) {
            const int c = wm * 32 + mt * 16 + h8 * 8 + (lane >> 2);
            const float g  = ln_g[c];
            const float bb = ln_b[c];
            float* rowp = out + ((size_t)b * NCH + c) * NPOS + n0 + wn * 32 + (lane & 3) * 2;
#pragma unroll
            for (int u = 0; u < 4; u++) {
                int col = wn * 32 + u * 8 + (lane & 3) * 2;
                float v0 = (acc[mt][u][h8 * 2]     - mu_s[col])     * rs_s[col]     * g + bb;
                float v1 = (acc[mt][u][h8 * 2 + 1] - mu_s[col + 1]) * rs_s[col + 1] * g + bb;
                *(float2*)(rowp + u * 8) = make_float2(v0, v1);
            }
        }
}

// =============================================================================
extern "C" void kernel_launch(void* const* d_in, const int* in_sizes, int n_in,
                              void* d_out, int out_size)
{
    const float* x     = (const float*)d_in[0];
    const float* w_qkv = (const float*)d_in[1];
    const float* w_out = (const float*)d_in[2];
    const float* b_out = (const float*)d_in[3];
    const float* ln_g  = (const float*)d_in[4];
    const float* ln_b  = (const float*)d_in[5];
    float* out = (float*)d_out;

    cudaFuncSetAttribute(k_qkv, cudaFuncAttributeMaxDynamicSharedMemorySize, 131072);
    cudaFuncSetAttribute(k_ctx, cudaFuncAttributeMaxDynamicSharedMemorySize, 165888);
    cudaFuncSetAttribute(k_w2,  cudaFuncAttributeMaxDynamicSharedMemorySize,  82944);
    cudaFuncSetAttribute(k_out, cudaFuncAttributeMaxDynamicSharedMemorySize, 100864);

    k_qkv<<<2048, 256, 131072>>>(x, w_qkv);
    k_ctx<<<2048, 256, 165888>>>();
    k_red<<<528, 128>>>();
    k_w2<<<16, 256, 82944>>>(w_out);
    k_out<<<4096, 256, 100864>>>(b_out, ln_g, ln_b, out);
}

// round 7
// speedup vs baseline: 1.0334x; 1.0334x over previous
#include <cuda_runtime.h>
#include <cuda_bf16.h>
#include <math.h>
#include <stdint.h>

#define NPOS 16384          // H*W
#define NB   16             // batch
#define NCH  128            // C == hidden

// ---------------- device scratch (allocation-free rule: __device__ globals) ----
__device__ uint32_t g_qhi [NB * NPOS * 64];      // q bf16-hi pairs    [b][n][ch/2]
__device__ uint32_t g_qlo [NB * NPOS * 64];      // q bf16-lo pairs
__device__ uint32_t g_ekhi[NB * NPOS * 64];      // exp(k) bf16-hi     [b][n][ch/2]
__device__ uint32_t g_eklo[NB * NPOS * 64];
__device__ uint32_t g_vhi [NB * NPOS * 64];      // v bf16-hi          [b][n][ch/2]
__device__ uint32_t g_vlo [NB * NPOS * 64];
__device__ float    g_part[NB * 32 * 4224];      // per (b,512-chunk): 4x1024 ctx + 128 se
__device__ float    g_ctx [NB * 4224];           // reduced
__device__ uint32_t g_W2hi[NB * NCH * 64];       // fused W2 bf16-hi   [b][c][ch/2]
__device__ uint32_t g_W2lo[NB * NCH * 64];

// ---------------- helpers -------------------------------------------------------
__device__ __forceinline__ uint32_t smem_u32(const void* p) {
    uint32_t a;
    asm("{ .reg .u64 t; cvta.to.shared.u64 t, %1; cvt.u32.u64 %0, t; }" : "=r"(a) : "l"(p));
    return a;
}
// swizzled byte offset within a 128-col bf16 tile (256B rows, XOR on 16B chunks)
__device__ __forceinline__ uint32_t toff(int r, int c) {
    return (uint32_t)(r * 256 + (((c >> 3) ^ (r & 7)) << 4) + ((c & 7) << 1));
}
__device__ __forceinline__ void ldsm4(uint32_t* r, uint32_t a) {
    asm volatile("ldmatrix.sync.aligned.m8n8.x4.shared.b16 {%0,%1,%2,%3}, [%4];"
                 : "=r"(r[0]), "=r"(r[1]), "=r"(r[2]), "=r"(r[3]) : "r"(a));
}
__device__ __forceinline__ void ldsm4t(uint32_t* r, uint32_t a) {
    asm volatile("ldmatrix.sync.aligned.m8n8.x4.trans.shared.b16 {%0,%1,%2,%3}, [%4];"
                 : "=r"(r[0]), "=r"(r[1]), "=r"(r[2]), "=r"(r[3]) : "r"(a));
}
__device__ __forceinline__ void mma16816(float* d, const uint32_t* a, uint32_t b0, uint32_t b1) {
    asm volatile(
        "mma.sync.aligned.m16n8k16.row.col.f32.bf16.bf16.f32 "
        "{%0,%1,%2,%3}, {%4,%5,%6,%7}, {%8,%9}, {%0,%1,%2,%3};"
        : "+f"(d[0]), "+f"(d[1]), "+f"(d[2]), "+f"(d[3])
        : "r"(a[0]), "r"(a[1]), "r"(a[2]), "r"(a[3]), "r"(b0), "r"(b1));
}
__device__ __forceinline__ void split_pair(float v0, float v1, uint32_t& hi, uint32_t& lo) {
    __nv_bfloat162 h = __float22bfloat162_rn(make_float2(v0, v1));
    float2 hf = __bfloat1622float2(h);
    __nv_bfloat162 l = __float22bfloat162_rn(make_float2(v0 - hf.x, v1 - hf.y));
    hi = *(uint32_t*)&h;
    lo = *(uint32_t*)&l;
}

// 128x128x128 warp-tiled GEMM pass.
template<bool ATRANS>
__device__ __forceinline__ void gemm128(float (&acc)[2][8][4], uint32_t aB, uint32_t bB,
                                        int wm, int wn, int lane)
{
    const int l7  = lane & 7;
    const int lb3 = (lane >> 3) & 1;
    const int lb4 = (lane >> 4) & 1;
#pragma unroll
    for (int k = 0; k < 8; k++) {
        uint32_t a[2][4];
#pragma unroll
        for (int t = 0; t < 2; t++) {
            uint32_t addr;
            if (ATRANS)
                addr = aB + toff(k * 16 + l7 + lb4 * 8, wm * 32 + t * 16 + lb3 * 8);
            else
                addr = aB + toff(wm * 32 + t * 16 + l7 + lb3 * 8, k * 16 + lb4 * 8);
            if (ATRANS) ldsm4t(a[t], addr); else ldsm4(a[t], addr);
        }
        uint32_t bf[4][4];
#pragma unroll
        for (int u2 = 0; u2 < 4; u2++)
            ldsm4(bf[u2], bB + toff(wn * 64 + u2 * 16 + l7 + lb4 * 8, k * 16 + lb3 * 8));
#pragma unroll
        for (int t = 0; t < 2; t++)
#pragma unroll
            for (int u = 0; u < 8; u++)
                mma16816(acc[t][u], a[t], bf[u >> 1][(u & 1) * 2], bf[u >> 1][(u & 1) * 2 + 1]);
    }
}

// load a 128x128 f32 tile (row stride strideF) into split bf16 hi/lo swizzled tiles
__device__ __forceinline__ void load_split(char* smc, int hiOff, int loOff,
                                           const float* __restrict__ src,
                                           int strideF, int tid)
{
#pragma unroll
    for (int i = 0; i < 16; i++) {
        int lin = tid + i * 256;
        int r = lin >> 5, cq = lin & 31;
        float4 v = *(const float4*)(src + (size_t)r * strideF + cq * 4);
        uint32_t h01, l01, h23, l23;
        split_pair(v.x, v.y, h01, l01);
        split_pair(v.z, v.w, h23, l23);
        uint32_t o = toff(r, cq * 4);
        *(uint32_t*)(smc + hiOff + o)     = h01;
        *(uint32_t*)(smc + hiOff + o + 4) = h23;
        *(uint32_t*)(smc + loOff + o)     = l01;
        *(uint32_t*)(smc + loOff + o + 4) = l23;
    }
}

// =============================================================================
// K1: qkv = w_qkv @ x via mma.sync bf16-split.  Fused q-softmax; k-chunk stores
// exp(k), v-chunk stores v, both as split-bf16 pairs [b][n][ch/2].
// smem: xs hi/lo 64K | ws hi/lo 64K = 131072 B
// =============================================================================
#define K1_XHI 0
#define K1_XLO 32768
#define K1_WHI 65536
#define K1_WLO 98304

__global__ __launch_bounds__(256, 1)
void k_qkv(const float* __restrict__ x, const float* __restrict__ w_qkv)
{
    extern __shared__ char smc[];
    const uint32_t sb = smem_u32(smc);
    const int tid = threadIdx.x;
    const int warp = tid >> 5, lane = tid & 31;
    const int wm = warp & 3, wn = warp >> 2;

    const int b  = blockIdx.x >> 7;
    const int n0 = (blockIdx.x & 127) << 7;

    load_split(smc, K1_XHI, K1_XLO, x + (size_t)b * NCH * NPOS + n0, NPOS, tid);
    load_split(smc, K1_WHI, K1_WLO, w_qkv, NCH, tid);
    __syncthreads();

    for (int chunk = 0; chunk < 3; chunk++) {
        float acc[2][8][4];
#pragma unroll
        for (int t = 0; t < 2; t++)
#pragma unroll
            for (int u = 0; u < 8; u++)
#pragma unroll
                for (int r = 0; r < 4; r++) acc[t][u][r] = 0.f;

        gemm128<true>(acc, sb + K1_XHI, sb + K1_WHI, wm, wn, lane);
        gemm128<true>(acc, sb + K1_XHI, sb + K1_WLO, wm, wn, lane);
        gemm128<true>(acc, sb + K1_XLO, sb + K1_WHI, wm, wn, lane);

        if (chunk == 0) {
            const float scale = 0.17677669529663687f; // 32^-0.5
#pragma unroll
            for (int t = 0; t < 2; t++)
#pragma unroll
            for (int rh = 0; rh < 2; rh++) {
                float e[8][2];
                float sA = 0.f, sB = 0.f;
#pragma unroll
                for (int u = 0; u < 8; u++)
#pragma unroll
                    for (int j = 0; j < 2; j++) {
                        float v = __expf(acc[t][u][rh * 2 + j]);
                        e[u][j] = v;
                        if (u < 4) sA += v; else sB += v;
                    }
                sA += __shfl_xor_sync(0xffffffffu, sA, 1);
                sA += __shfl_xor_sync(0xffffffffu, sA, 2);
                sB += __shfl_xor_sync(0xffffffffu, sB, 1);
                sB += __shfl_xor_sync(0xffffffffu, sB, 2);
                const float invA = scale / sA, invB = scale / sB;
                const int p = wm * 32 + t * 16 + rh * 8 + (lane >> 2);
                const size_t rowb = ((size_t)b * NPOS + n0 + p) * 64;
#pragma unroll
                for (int u = 0; u < 8; u++) {
                    float inv = (u < 4) ? invA : invB;
                    uint32_t hi, lo;
                    split_pair(e[u][0] * inv, e[u][1] * inv, hi, lo);
                    int cp = wn * 32 + u * 4 + (lane & 3);
                    g_qhi[rowb + cp] = hi;
                    g_qlo[rowb + cp] = lo;
                }
            }
        } else {
            uint32_t* ghi = (chunk == 1) ? g_ekhi : g_vhi;
            uint32_t* glo = (chunk == 1) ? g_eklo : g_vlo;
#pragma unroll
            for (int t = 0; t < 2; t++)
#pragma unroll
            for (int rh = 0; rh < 2; rh++) {
                const int p = wm * 32 + t * 16 + rh * 8 + (lane >> 2);
                const size_t rowb = ((size_t)b * NPOS + n0 + p) * 64;
#pragma unroll
                for (int u = 0; u < 8; u++) {
                    float v0 = acc[t][u][rh * 2], v1 = acc[t][u][rh * 2 + 1];
                    if (chunk == 1) { v0 = __expf(v0); v1 = __expf(v1); }
                    uint32_t hi, lo;
                    split_pair(v0, v1, hi, lo);
                    int cp = wn * 32 + u * 4 + (lane & 3);
                    ghi[rowb + cp] = hi;
                    glo[rowb + cp] = lo;
                }
            }
        }

        __syncthreads();
        if (chunk < 2) {
            load_split(smc, K1_WHI, K1_WLO, w_qkv + (size_t)(chunk + 1) * 128 * NCH, NCH, tid);
            __syncthreads();
        }
    }
}

// =============================================================================
// K2a: block = (b, 512-n chunk) = 512 blocks.  4 iterations of 128 rows,
// accumulating ctx in registers; sumexp folded into loads.
// smem: ek hi/lo 64K | v hi/lo 64K | red 32K | se 2K = 165,888 B
// =============================================================================
#define C_EKHI 0
#define C_EKLO 32768
#define C_VHI  65536
#define C_VLO  98304
#define C_RED  131072
#define C_SE   163840

__global__ __launch_bounds__(256, 1)
void k_ctx()
{
    extern __shared__ char smc[];
    const uint32_t sb = smem_u32(smc);
    const int tid = threadIdx.x;
    const int warp = tid >> 5, lane = tid & 31;
    const int b   = blockIdx.x >> 5;
    const int ck0 = (blockIdx.x & 31) * 4;       // 4 subchunks of 128 rows

    const int cp = tid & 63;                      // fixed channel-pair per thread
    float s0 = 0.f, s1 = 0.f;

    const int h = warp & 3, ks = warp >> 2;
    const int l7 = lane & 7, lb3 = (lane >> 3) & 1, lb4 = (lane >> 4) & 1;

    float acc[2][4][4];
#pragma unroll
    for (int mt = 0; mt < 2; mt++)
#pragma unroll
        for (int u = 0; u < 4; u++)
#pragma unroll
            for (int r = 0; r < 4; r++) acc[mt][u][r] = 0.f;

    const int PA[3] = {C_EKHI, C_EKHI, C_EKLO};
    const int PB[3] = {C_VHI,  C_VLO,  C_VHI};

    for (int it = 0; it < 4; it++) {
        const size_t rowbase = ((size_t)b * NPOS + (size_t)(ck0 + it) * 128) * 64;
#pragma unroll
        for (int i = 0; i < 32; i++) {
            int r = (tid >> 6) + i * 4;
            uint32_t u = g_ekhi[rowbase + (size_t)r * 64 + cp];
            *(uint32_t*)(smc + C_EKHI + toff(r, cp * 2)) = u;
            float2 f = __bfloat1622float2(*(__nv_bfloat162*)&u);
            s0 += f.x; s1 += f.y;
        }
#pragma unroll
        for (int i = 0; i < 32; i++) {
            int r = (tid >> 6) + i * 4;
            uint32_t u = g_eklo[rowbase + (size_t)r * 64 + cp];
            *(uint32_t*)(smc + C_EKLO + toff(r, cp * 2)) = u;
            float2 f = __bfloat1622float2(*(__nv_bfloat162*)&u);
            s0 += f.x; s1 += f.y;
        }
#pragma unroll
        for (int i = 0; i < 32; i++) {
            int r = (tid >> 6) + i * 4;
            *(uint32_t*)(smc + C_VHI + toff(r, cp * 2)) = g_vhi[rowbase + (size_t)r * 64 + cp];
            *(uint32_t*)(smc + C_VLO + toff(r, cp * 2)) = g_vlo[rowbase + (size_t)r * 64 + cp];
        }
        __syncthreads();

#pragma unroll
        for (int ps = 0; ps < 3; ps++) {
            const uint32_t aB = sb + PA[ps], bB = sb + PB[ps];
#pragma unroll
            for (int kk = 0; kk < 4; kk++) {
                const int p0 = ks * 64 + kk * 16;
                uint32_t a[2][4];
#pragma unroll
                for (int mt = 0; mt < 2; mt++)
                    ldsm4t(a[mt], aB + toff(p0 + l7 + lb4 * 8, h * 32 + mt * 16 + lb3 * 8));
                uint32_t bfr[2][4];
#pragma unroll
                for (int nt = 0; nt < 2; nt++)
                    ldsm4t(bfr[nt], bB + toff(p0 + l7 + lb3 * 8, h * 32 + nt * 16 + lb4 * 8));
#pragma unroll
                for (int mt = 0; mt < 2; mt++)
#pragma unroll
                    for (int u = 0; u < 4; u++)
                        mma16816(acc[mt][u], a[mt], bfr[u >> 1][(u & 1) * 2],
                                 bfr[u >> 1][(u & 1) * 2 + 1]);
            }
        }
        __syncthreads();
    }

    // stage per-warp ctx fragments, combine the 2 k-slices
    {
        float* rb = (float*)(smc + C_RED) + ks * 4096 + h * 1024;
#pragma unroll
        for (int mt = 0; mt < 2; mt++)
#pragma unroll
            for (int u = 0; u < 4; u++) {
                int dr = mt * 16 + (lane >> 2), e = u * 8 + (lane & 3) * 2;
                rb[dr * 32 + e]           = acc[mt][u][0];
                rb[dr * 32 + e + 1]       = acc[mt][u][1];
                rb[(dr + 8) * 32 + e]     = acc[mt][u][2];
                rb[(dr + 8) * 32 + e + 1] = acc[mt][u][3];
            }
        float* se = (float*)(smc + C_SE);
        se[(tid >> 6) * 128 + cp * 2]     = s0;
        se[(tid >> 6) * 128 + cp * 2 + 1] = s1;
    }
    __syncthreads();

    const size_t pbase = (size_t)blockIdx.x * 4224;
    const float* r0 = (const float*)(smc + C_RED);
    for (int idx = tid; idx < 4096; idx += 256)
        g_part[pbase + idx] = r0[idx] + r0[4096 + idx];
    if (tid < 128) {
        const float* se = (const float*)(smc + C_SE);
        g_part[pbase + 4096 + tid] = se[tid] + se[128 + tid] + se[256 + tid] + se[384 + tid];
    }
}

// =============================================================================
// K2b-1: reduce 32 chunk partials -> g_ctx[b][4224]
// =============================================================================
__global__ __launch_bounds__(128, 8)
void k_red()
{
    const int b = blockIdx.x / 33, sc = blockIdx.x % 33;
    const int slot = sc * 128 + threadIdx.x;
    const float* src = g_part + (size_t)b * 32 * 4224 + slot;
    float s = 0.f;
#pragma unroll 4
    for (int ckk = 0; ckk < 32; ckk++) s += src[(size_t)ckk * 4224];
    g_ctx[b * 4224 + slot] = s;
}

// =============================================================================
// K2b-2: normalize ctx, build fused W2 = w_out x ctx_norm, split bf16.
// grid = NB*8: block handles (b, 16 c-rows).  static smem ~26 KB, 4 CTAs/SM.
// =============================================================================
__global__ __launch_bounds__(256, 4)
void k_w2(const float* __restrict__ w_out)
{
    __shared__ float ctxs[4224];     // [h][d][33]
    __shared__ float Ss[128];
    __shared__ float ws2[2048];      // 16 c-rows x 128 ch

    const int b  = blockIdx.x >> 3;
    const int c0 = (blockIdx.x & 7) * 16;
    const int tid = threadIdx.x;

    for (int lin = tid; lin < 2048; lin += 256)
        ws2[lin] = w_out[(size_t)(c0 + (lin >> 7)) * 128 + (lin & 127)];
    for (int idx = tid; idx < 4096; idx += 256) {
        int h = idx >> 10, de = idx & 1023;
        ctxs[h * 1056 + (de >> 5) * 33 + (de & 31)] = g_ctx[b * 4224 + idx];
    }
    if (tid < 128) Ss[tid] = 1.0f / g_ctx[b * 4224 + 4096 + tid];
    __syncthreads();

    for (int oidx = tid; oidx < 1024; oidx += 256) {
        int cl = oidx >> 6, cpp = oidx & 63;
        int ch0 = cpp * 2;
        int h = ch0 >> 5, d = ch0 & 31;
        const float* cr0 = &ctxs[h * 1056 + d * 33];
        const float* cr1 = cr0 + 33;
        const float* wr  = &ws2[cl * 128 + h * 32];
        float a0 = 0.f, a1 = 0.f;
#pragma unroll
        for (int e = 0; e < 32; e++) {
            a0 = fmaf(wr[e], cr0[e], a0);
            a1 = fmaf(wr[e], cr1[e], a1);
        }
        uint32_t hi, lo;
        split_pair(a0 * Ss[ch0], a1 * Ss[ch0 + 1], hi, lo);
        size_t dst = (size_t)b * 8192 + (size_t)(c0 + cl) * 64 + cpp;
        g_W2hi[dst] = hi;
        g_W2lo[dst] = lo;
    }
}

// =============================================================================
// K3: y = W2_b @ q + b_out via mma.sync bf16-split, LayerNorm over C fused.
// 64 positions per block -> 2 CTAs/SM.  M=128 c, N=64 p.
// smem: W2 hi/lo 64K | q hi/lo 32K | red 2K | stats 0.5K = 100,864 B
// =============================================================================
#define K3_WHI 0
#define K3_WLO 32768
#define K3_QHI 65536
#define K3_QLO 81920
#define K3_RS  98304
#define K3_RQ  99328
#define K3_MU  100352
#define K3_RST 100608

__global__ __launch_bounds__(256, 2)
void k_out(const float* __restrict__ b_out, const float* __restrict__ ln_g,
           const float* __restrict__ ln_b, float* __restrict__ out)
{
    extern __shared__ char smc[];
    const uint32_t sb = smem_u32(smc);
    float* red_s = (float*)(smc + K3_RS);    // [4][64]
    float* red_q = (float*)(smc + K3_RQ);    // [4][64]
    float* mu_s  = (float*)(smc + K3_MU);    // [64]
    float* rs_s  = (float*)(smc + K3_RST);   // [64]

    const int tid = threadIdx.x;
    const int warp = tid >> 5, lane = tid & 31;
    const int wm = warp & 3, wn = warp >> 2;          // wn in {0,1}
    const int b  = blockIdx.x >> 8;
    const int n0 = (blockIdx.x & 255) << 6;

#pragma unroll
    for (int i = 0; i < 32; i++) {
        int it = tid + i * 256;              // 8192: W2 tile [c][ch]
        int r = it >> 6, cpp = it & 63;
        uint32_t o = toff(r, cpp * 2);
        *(uint32_t*)(smc + K3_WHI + o) = g_W2hi[(size_t)b * 8192 + it];
        *(uint32_t*)(smc + K3_WLO + o) = g_W2lo[(size_t)b * 8192 + it];
    }
#pragma unroll
    for (int i = 0; i < 16; i++) {
        int it = tid + i * 256;              // 4096: q tile [p<64][ch]
        int r = it >> 6, cpp = it & 63;
        uint32_t o = toff(r, cpp * 2);
        size_t src = ((size_t)b * NPOS + n0 + r) * 64 + cpp;
        *(uint32_t*)(smc + K3_QHI + o) = g_qhi[src];
        *(uint32_t*)(smc + K3_QLO + o) = g_qlo[src];
    }
    __syncthreads();

    const int l7 = lane & 7, lb3 = (lane >> 3) & 1, lb4 = (lane >> 4) & 1;
    float acc[2][4][4];
#pragma unroll
    for (int mt = 0; mt < 2; mt++)
#pragma unroll
        for (int u = 0; u < 4; u++)
#pragma unroll
            for (int r = 0; r < 4; r++) acc[mt][u][r] = 0.f;

    const int PA[3] = {K3_WHI, K3_WHI, K3_WLO};
    const int PB[3] = {K3_QHI, K3_QLO, K3_QHI};
#pragma unroll
    for (int ps = 0; ps < 3; ps++) {
        const uint32_t aB = sb + PA[ps], bB = sb + PB[ps];
#pragma unroll
        for (int k = 0; k < 8; k++) {
            uint32_t a[2][4];
#pragma unroll
            for (int mt = 0; mt < 2; mt++)
                ldsm4(a[mt], aB + toff(wm * 32 + mt * 16 + l7 + lb3 * 8, k * 16 + lb4 * 8));
            uint32_t bfr[2][4];
#pragma unroll
            for (int nt = 0; nt < 2; nt++)
                ldsm4(bfr[nt], bB + toff(wn * 32 + nt * 16 + l7 + lb4 * 8, k * 16 + lb3 * 8));
#pragma unroll
            for (int mt = 0; mt < 2; mt++)
#pragma unroll
                for (int u = 0; u < 4; u++)
                    mma16816(acc[mt][u], a[mt], bfr[u >> 1][(u & 1) * 2], bfr[u >> 1][(u & 1) * 2 + 1]);
        }
    }

    // bias
#pragma unroll
    for (int mt = 0; mt < 2; mt++)
#pragma unroll
        for (int h8 = 0; h8 < 2; h8++) {
            const float bo = b_out[wm * 32 + mt * 16 + h8 * 8 + (lane >> 2)];
#pragma unroll
            for (int u = 0; u < 4; u++) {
                acc[mt][u][h8 * 2]     += bo;
                acc[mt][u][h8 * 2 + 1] += bo;
            }
        }

    // LN partials: column sums over this warp's 32 c-rows
#pragma unroll
    for (int u = 0; u < 4; u++)
#pragma unroll
        for (int j = 0; j < 2; j++) {
            float a0 = acc[0][u][j],     a1 = acc[0][u][2 + j];
            float a2 = acc[1][u][j],     a3 = acc[1][u][2 + j];
            float s = a0 + a1 + a2 + a3;
            float q = a0 * a0 + a1 * a1 + a2 * a2 + a3 * a3;
            s += __shfl_xor_sync(0xffffffffu, s, 4);
            q += __shfl_xor_sync(0xffffffffu, q, 4);
            s += __shfl_xor_sync(0xffffffffu, s, 8);
            q += __shfl_xor_sync(0xffffffffu, q, 8);
            s += __shfl_xor_sync(0xffffffffu, s, 16);
            q += __shfl_xor_sync(0xffffffffu, q, 16);
            if ((lane >> 2) == 0) {
                int col = wn * 32 + u * 8 + (lane & 3) * 2 + j;
                red_s[wm * 64 + col] = s;
                red_q[wm * 64 + col] = q;
            }
        }
    __syncthreads();

    if (tid < 64) {
        float s = red_s[tid] + red_s[64 + tid] + red_s[128 + tid] + red_s[192 + tid];
        float q = red_q[tid] + red_q[64 + tid] + red_q[128 + tid] + red_q[192 + tid];
        float mu  = s * (1.0f / 128.0f);
        float var = q * (1.0f / 128.0f) - mu * mu;
        mu_s[tid] = mu;
        rs_s[tid] = rsqrtf(var + 1e-5f);
    }
    __syncthreads();

#pragma unroll
    for (int mt = 0; mt < 2; mt++)
#pragma unroll
        for (int h8 = 0; h8 < 2; h8++) {
            const int c = wm * 32 + mt * 16 + h8 * 8 + (lane >> 2);
            const float g  = ln_g[c];
            const float bb = ln_b[c];
            float* rowp = out + ((size_t)b * NCH + c) * NPOS + n0 + wn * 32 + (lane & 3) * 2;
#pragma unroll
            for (int u = 0; u < 4; u++) {
                int col = wn * 32 + u * 8 + (lane & 3) * 2;
                float v0 = (acc[mt][u][h8 * 2]     - mu_s[col])     * rs_s[col]     * g + bb;
                float v1 = (acc[mt][u][h8 * 2 + 1] - mu_s[col + 1]) * rs_s[col + 1] * g + bb;
                *(float2*)(rowp + u * 8) = make_float2(v0, v1);
            }
        }
}

// =============================================================================
extern "C" void kernel_launch(void* const* d_in, const int* in_sizes, int n_in,
                              void* d_out, int out_size)
{
    const float* x     = (const float*)d_in[0];
    const float* w_qkv = (const float*)d_in[1];
    const float* w_out = (const float*)d_in[2];
    const float* b_out = (const float*)d_in[3];
    const float* ln_g  = (const float*)d_in[4];
    const float* ln_b  = (const float*)d_in[5];
    float* out = (float*)d_out;

    cudaFuncSetAttribute(k_qkv, cudaFuncAttributeMaxDynamicSharedMemorySize, 131072);
    cudaFuncSetAttribute(k_ctx, cudaFuncAttributeMaxDynamicSharedMemorySize, 165888);
    cudaFuncSetAttribute(k_out, cudaFuncAttributeMaxDynamicSharedMemorySize, 100864);

    k_qkv<<<2048, 256, 131072>>>(x, w_qkv);
    k_ctx<<<512, 256, 165888>>>();
    k_red<<<528, 128>>>();
    k_w2<<<128, 256>>>(w_out);
    k_out<<<4096, 256, 100864>>>(b_out, ln_g, ln_b, out);
}

// round 8
// speedup vs baseline: 1.1019x; 1.0663x over previous
#include <cuda_runtime.h>
#include <cuda_bf16.h>
#include <math.h>
#include <stdint.h>

#define NPOS 16384          // H*W
#define NB   16             // batch
#define NCH  128            // C == hidden
#define NTILE (NB * NPOS / 64)   // 4096 64-row tiles

// ---------------- device scratch (allocation-free rule: __device__ globals) ----
// q/ek/v stored as swizzled 64x128 bf16 tiles: [tile][4096 u32], tile=(b*NPOS+n)/64
__device__ uint32_t g_qhi [NTILE * 4096];
__device__ uint32_t g_qlo [NTILE * 4096];
__device__ uint32_t g_ekhi[NTILE * 4096];
__device__ uint32_t g_eklo[NTILE * 4096];
__device__ uint32_t g_vhi [NTILE * 4096];
__device__ uint32_t g_vlo [NTILE * 4096];
__device__ float    g_part[NB * 32 * 4224];      // per (b,512-chunk): 4x1024 ctx + 128 se
__device__ float    g_ctx [NB * 4224];           // reduced
// W2 stored as swizzled 128x128 bf16 tiles per b: [b][8192 u32]
__device__ uint32_t g_W2hi[NB * 8192];
__device__ uint32_t g_W2lo[NB * 8192];
// w_qkv pre-split + pre-swizzled: 3 chunks of 128x128
__device__ uint32_t g_wswh[3 * 8192];
__device__ uint32_t g_wswl[3 * 8192];

// ---------------- helpers -------------------------------------------------------
__device__ __forceinline__ uint32_t smem_u32(const void* p) {
    uint32_t a;
    asm("{ .reg .u64 t; cvta.to.shared.u64 t, %1; cvt.u32.u64 %0, t; }" : "=r"(a) : "l"(p));
    return a;
}
// swizzled byte offset within a 128-col bf16 tile (256B rows, XOR on 16B chunks)
__device__ __forceinline__ uint32_t toff(int r, int c) {
    return (uint32_t)(r * 256 + (((c >> 3) ^ (r & 7)) << 4) + ((c & 7) << 1));
}
// swizzled byte offset within a 64-col bf16 tile (128B rows)
__device__ __forceinline__ uint32_t toff64(int r, int c) {
    return (uint32_t)(r * 128 + (((c >> 3) ^ (r & 7)) << 4) + ((c & 7) << 1));
}
__device__ __forceinline__ void ldsm4(uint32_t* r, uint32_t a) {
    asm volatile("ldmatrix.sync.aligned.m8n8.x4.shared.b16 {%0,%1,%2,%3}, [%4];"
                 : "=r"(r[0]), "=r"(r[1]), "=r"(r[2]), "=r"(r[3]) : "r"(a));
}
__device__ __forceinline__ void ldsm4t(uint32_t* r, uint32_t a) {
    asm volatile("ldmatrix.sync.aligned.m8n8.x4.trans.shared.b16 {%0,%1,%2,%3}, [%4];"
                 : "=r"(r[0]), "=r"(r[1]), "=r"(r[2]), "=r"(r[3]) : "r"(a));
}
__device__ __forceinline__ void mma16816(float* d, const uint32_t* a, uint32_t b0, uint32_t b1) {
    asm volatile(
        "mma.sync.aligned.m16n8k16.row.col.f32.bf16.bf16.f32 "
        "{%0,%1,%2,%3}, {%4,%5,%6,%7}, {%8,%9}, {%0,%1,%2,%3};"
        : "+f"(d[0]), "+f"(d[1]), "+f"(d[2]), "+f"(d[3])
        : "r"(a[0]), "r"(a[1]), "r"(a[2]), "r"(a[3]), "r"(b0), "r"(b1));
}
__device__ __forceinline__ void split_pair(float v0, float v1, uint32_t& hi, uint32_t& lo) {
    __nv_bfloat162 h = __float22bfloat162_rn(make_float2(v0, v1));
    float2 hf = __bfloat1622float2(h);
    __nv_bfloat162 l = __float22bfloat162_rn(make_float2(v0 - hf.x, v1 - hf.y));
    hi = *(uint32_t*)&h;
    lo = *(uint32_t*)&l;
}

// =============================================================================
// K0: pre-split + pre-swizzle w_qkv into 3 chunks of 128x128 bf16 tiles
// =============================================================================
__global__ __launch_bounds__(256)
void k_prep(const float* __restrict__ w_qkv)
{
    int idx = blockIdx.x * 256 + threadIdx.x;   // 24576 items
    int chunk = idx >> 13, rem = idx & 8191;
    int o = rem >> 6, cp = rem & 63;
    int c0 = cp * 2;
    float v0 = w_qkv[(size_t)(chunk * 128 + o) * NCH + c0];
    float v1 = w_qkv[(size_t)(chunk * 128 + o) * NCH + c0 + 1];
    uint32_t hi, lo;
    split_pair(v0, v1, hi, lo);
    uint32_t d = (uint32_t)chunk * 8192 + (toff(o, c0) >> 2);
    g_wswh[d] = hi;
    g_wswl[d] = lo;
}

// =============================================================================
// K1: qkv = w_qkv @ x via mma.sync bf16-split.  64 positions/block, 4096 blocks,
// 2 CTAs/SM.  M=64 pos (A = x via trans-ldsm), N=128 out-ch (B = w, pre-split).
// Epilogue writes q/ek/v directly into swizzled global tiles.
// smem: x hi/lo 32K | w hi/lo 64K = 98304 B
// =============================================================================
#define Q1_XHI 0
#define Q1_XLO 16384
#define Q1_WHI 32768
#define Q1_WLO 65536

__global__ __launch_bounds__(256, 2)
void k_qkv(const float* __restrict__ x)
{
    extern __shared__ char smc[];
    const uint32_t sb = smem_u32(smc);
    const int tid = threadIdx.x;
    const int warp = tid >> 5, lane = tid & 31;
    const int wm = warp & 1, wn = warp >> 1;        // wm: 2x32 pos, wn: 4x32 ch

    const int b    = blockIdx.x >> 8;
    const int tile = blockIdx.x & 255;
    const int n0   = tile << 6;
    const uint32_t gt = (uint32_t)(b * 256 + tile);  // global tile index

    // ---- load x tile [c=128 rows][p=64 cols], split bf16, toff64 swizzle ----
    {
        const float* xb = x + (size_t)b * NCH * NPOS + n0;
#pragma unroll
        for (int i = 0; i < 8; i++) {
            int lin = tid + i * 256;            // 2048 float4
            int c = lin >> 4, pq = lin & 15;
            float4 v = *(const float4*)(xb + (size_t)c * NPOS + pq * 4);
            uint32_t h01, l01, h23, l23;
            split_pair(v.x, v.y, h01, l01);
            split_pair(v.z, v.w, h23, l23);
            uint32_t o = toff64(c, pq * 4);
            *(uint32_t*)(smc + Q1_XHI + o)     = h01;
            *(uint32_t*)(smc + Q1_XHI + o + 4) = h23;
            *(uint32_t*)(smc + Q1_XLO + o)     = l01;
            *(uint32_t*)(smc + Q1_XLO + o + 4) = l23;
        }
    }
    // ---- copy w chunk0 (pre-swizzled) ----
#pragma unroll
    for (int i = 0; i < 8; i++) {
        int lin = tid + i * 256;                // 2048 uint4
        ((uint4*)(smc + Q1_WHI))[lin] = ((const uint4*)g_wswh)[lin];
        ((uint4*)(smc + Q1_WLO))[lin] = ((const uint4*)g_wswl)[lin];
    }
    __syncthreads();

    const int l7 = lane & 7, lb3 = (lane >> 3) & 1, lb4 = (lane >> 4) & 1;
    const float scale = 0.17677669529663687f;   // 32^-0.5

    for (int chunk = 0; chunk < 3; chunk++) {
        float acc[2][4][4];
#pragma unroll
        for (int mt = 0; mt < 2; mt++)
#pragma unroll
            for (int u = 0; u < 4; u++)
#pragma unroll
                for (int r = 0; r < 4; r++) acc[mt][u][r] = 0.f;

        const int PA[3] = {Q1_XHI, Q1_XHI, Q1_XLO};
        const int PB[3] = {Q1_WHI, Q1_WLO, Q1_WHI};
#pragma unroll
        for (int ps = 0; ps < 3; ps++) {
            const uint32_t aB = sb + PA[ps], bB = sb + PB[ps];
#pragma unroll
            for (int k = 0; k < 8; k++) {
                uint32_t a[2][4];
#pragma unroll
                for (int mt = 0; mt < 2; mt++)
                    ldsm4t(a[mt], aB + toff64(k * 16 + l7 + lb4 * 8, wm * 32 + mt * 16 + lb3 * 8));
                uint32_t bfr[2][4];
#pragma unroll
                for (int nt = 0; nt < 2; nt++)
                    ldsm4(bfr[nt], bB + toff(wn * 32 + nt * 16 + l7 + lb4 * 8, k * 16 + lb3 * 8));
#pragma unroll
                for (int mt = 0; mt < 2; mt++)
#pragma unroll
                    for (int u = 0; u < 4; u++)
                        mma16816(acc[mt][u], a[mt], bfr[u >> 1][(u & 1) * 2],
                                 bfr[u >> 1][(u & 1) * 2 + 1]);
            }
        }

        // ---- epilogue: rows p = positions, cols = channels (head = wn) ----
        if (chunk == 0) {
#pragma unroll
            for (int mt = 0; mt < 2; mt++)
#pragma unroll
            for (int h8 = 0; h8 < 2; h8++) {
                float e[4][2];
                float s = 0.f;
#pragma unroll
                for (int u = 0; u < 4; u++)
#pragma unroll
                    for (int j = 0; j < 2; j++) {
                        float v = __expf(acc[mt][u][h8 * 2 + j]);
                        e[u][j] = v;
                        s += v;
                    }
                s += __shfl_xor_sync(0xffffffffu, s, 1);
                s += __shfl_xor_sync(0xffffffffu, s, 2);
                const float inv = scale / s;
                const int p = wm * 32 + mt * 16 + h8 * 8 + (lane >> 2);
#pragma unroll
                for (int u = 0; u < 4; u++) {
                    uint32_t hi, lo;
                    split_pair(e[u][0] * inv, e[u][1] * inv, hi, lo);
                    int ch0 = wn * 32 + u * 8 + (lane & 3) * 2;
                    uint32_t d = gt * 4096 + (toff(p, ch0) >> 2);
                    g_qhi[d] = hi;
                    g_qlo[d] = lo;
                }
            }
        } else {
            uint32_t* ghi = (chunk == 1) ? g_ekhi : g_vhi;
            uint32_t* glo = (chunk == 1) ? g_eklo : g_vlo;
#pragma unroll
            for (int mt = 0; mt < 2; mt++)
#pragma unroll
            for (int h8 = 0; h8 < 2; h8++) {
                const int p = wm * 32 + mt * 16 + h8 * 8 + (lane >> 2);
#pragma unroll
                for (int u = 0; u < 4; u++) {
                    float v0 = acc[mt][u][h8 * 2], v1 = acc[mt][u][h8 * 2 + 1];
                    if (chunk == 1) { v0 = __expf(v0); v1 = __expf(v1); }
                    uint32_t hi, lo;
                    split_pair(v0, v1, hi, lo);
                    int ch0 = wn * 32 + u * 8 + (lane & 3) * 2;
                    uint32_t d = gt * 4096 + (toff(p, ch0) >> 2);
                    ghi[d] = hi;
                    glo[d] = lo;
                }
            }
        }

        __syncthreads();
        if (chunk < 2) {
#pragma unroll
            for (int i = 0; i < 8; i++) {
                int lin = tid + i * 256;
                ((uint4*)(smc + Q1_WHI))[lin] = ((const uint4*)g_wswh)[(chunk + 1) * 2048 + lin];
                ((uint4*)(smc + Q1_WLO))[lin] = ((const uint4*)g_wswl)[(chunk + 1) * 2048 + lin];
            }
            __syncthreads();
        }
    }
}

// =============================================================================
// K2a: block = (b, 512-n chunk), 512 blocks, 2 CTAs/SM.  8 iterations of 64-row
// swizzled tiles (straight uint4 copies), ctx accumulated in registers,
// sumexp folded into copy (fixed-channel thread mapping).
// smem: ek hi/lo 32K | v hi/lo 32K | red 32K | se 8K = 106,496 B
// =============================================================================
#define C2_EKHI 0
#define C2_EKLO 16384
#define C2_VHI  32768
#define C2_VLO  49152
#define C2_RED  65536
#define C2_SE   98304

__global__ __launch_bounds__(256, 2)
void k_ctx()
{
    extern __shared__ char smc[];
    const uint32_t sb = smem_u32(smc);
    const int tid = threadIdx.x;
    const int warp = tid >> 5, lane = tid & 31;
    const int b   = blockIdx.x >> 5;
    const int ck  = blockIdx.x & 31;
    const int tbase = b * 256 + ck * 8;          // 8 consecutive 64-row tiles

    const int lc  = tid & 15;                    // fixed logical 16B-chunk col (8 ch)
    const int g16 = tid >> 4;
    float se_acc[8];
#pragma unroll
    for (int m = 0; m < 8; m++) se_acc[m] = 0.f;

    const int h = warp & 3, ks = warp >> 2;
    const int l7 = lane & 7, lb3 = (lane >> 3) & 1, lb4 = (lane >> 4) & 1;

    float acc[2][4][4];
#pragma unroll
    for (int mt = 0; mt < 2; mt++)
#pragma unroll
        for (int u = 0; u < 4; u++)
#pragma unroll
            for (int r = 0; r < 4; r++) acc[mt][u][r] = 0.f;

    const int PA[3] = {C2_EKHI, C2_EKHI, C2_EKLO};
    const int PB[3] = {C2_VHI,  C2_VLO,  C2_VHI};

    for (int it = 0; it < 8; it++) {
        const size_t tb = (size_t)(tbase + it) * 1024;   // uint4 base of tile
#pragma unroll
        for (int i = 0; i < 4; i++) {
            int r = g16 * 4 + i;
            int idx = r * 16 + (lc ^ (r & 7));           // swizzled uint4 index
            uint4 eh = ((const uint4*)g_ekhi)[tb + idx];
            uint4 el = ((const uint4*)g_eklo)[tb + idx];
            ((uint4*)(smc + C2_EKHI))[idx] = eh;
            ((uint4*)(smc + C2_EKLO))[idx] = el;
            ((uint4*)(smc + C2_VHI))[idx] = ((const uint4*)g_vhi)[tb + idx];
            ((uint4*)(smc + C2_VLO))[idx] = ((const uint4*)g_vlo)[tb + idx];
            const uint32_t* ehp = (const uint32_t*)&eh;
            const uint32_t* elp = (const uint32_t*)&el;
#pragma unroll
            for (int w = 0; w < 4; w++) {
                float2 fh = __bfloat1622float2(*(__nv_bfloat162*)&ehp[w]);
                float2 fl = __bfloat1622float2(*(__nv_bfloat162*)&elp[w]);
                se_acc[w * 2]     += fh.x + fl.x;
                se_acc[w * 2 + 1] += fh.y + fl.y;
            }
        }
        __syncthreads();

#pragma unroll
        for (int ps = 0; ps < 3; ps++) {
            const uint32_t aB = sb + PA[ps], bB = sb + PB[ps];
#pragma unroll
            for (int kk = 0; kk < 2; kk++) {
                const int p0 = ks * 32 + kk * 16;
                uint32_t a[2][4];
#pragma unroll
                for (int mt = 0; mt < 2; mt++)
                    ldsm4t(a[mt], aB + toff(p0 + l7 + lb4 * 8, h * 32 + mt * 16 + lb3 * 8));
                uint32_t bfr[2][4];
#pragma unroll
                for (int nt = 0; nt < 2; nt++)
                    ldsm4t(bfr[nt], bB + toff(p0 + l7 + lb3 * 8, h * 32 + nt * 16 + lb4 * 8));
#pragma unroll
                for (int mt = 0; mt < 2; mt++)
#pragma unroll
                    for (int u = 0; u < 4; u++)
                        mma16816(acc[mt][u], a[mt], bfr[u >> 1][(u & 1) * 2],
                                 bfr[u >> 1][(u & 1) * 2 + 1]);
            }
        }
        __syncthreads();
    }

    // stage per-warp ctx fragments and per-group sumexp
    {
        float* rb = (float*)(smc + C2_RED) + ks * 4096 + h * 1024;
#pragma unroll
        for (int mt = 0; mt < 2; mt++)
#pragma unroll
            for (int u = 0; u < 4; u++) {
                int dr = mt * 16 + (lane >> 2), e = u * 8 + (lane & 3) * 2;
                rb[dr * 32 + e]           = acc[mt][u][0];
                rb[dr * 32 + e + 1]       = acc[mt][u][1];
                rb[(dr + 8) * 32 + e]     = acc[mt][u][2];
                rb[(dr + 8) * 32 + e + 1] = acc[mt][u][3];
            }
        float* se = (float*)(smc + C2_SE);
#pragma unroll
        for (int m = 0; m < 8; m++)
            se[g16 * 128 + lc * 8 + m] = se_acc[m];
    }
    __syncthreads();

    const size_t pbase = (size_t)blockIdx.x * 4224;
    const float* r0 = (const float*)(smc + C2_RED);
    for (int idx = tid; idx < 4096; idx += 256)
        g_part[pbase + idx] = r0[idx] + r0[4096 + idx];
    if (tid < 128) {
        const float* se = (const float*)(smc + C2_SE);
        float s = 0.f;
#pragma unroll
        for (int g = 0; g < 16; g++) s += se[g * 128 + tid];
        g_part[pbase + 4096 + tid] = s;
    }
}

// =============================================================================
// K2b-1: reduce 32 chunk partials -> g_ctx[b][4224]
// =============================================================================
__global__ __launch_bounds__(128, 8)
void k_red()
{
    const int b = blockIdx.x / 33, sc = blockIdx.x % 33;
    const int slot = sc * 128 + threadIdx.x;
    const float* src = g_part + (size_t)b * 32 * 4224 + slot;
    float s = 0.f;
#pragma unroll 4
    for (int ckk = 0; ckk < 32; ckk++) s += src[(size_t)ckk * 4224];
    g_ctx[b * 4224 + slot] = s;
}

// =============================================================================
// K2b-2: normalize ctx, build fused W2, write as swizzled bf16 tiles per b.
// =============================================================================
__global__ __launch_bounds__(256, 4)
void k_w2(const float* __restrict__ w_out)
{
    __shared__ float ctxs[4224];     // [h][d][33]
    __shared__ float Ss[128];
    __shared__ float ws2[2048];      // 16 c-rows x 128 ch

    const int b  = blockIdx.x >> 3;
    const int c0 = (blockIdx.x & 7) * 16;
    const int tid = threadIdx.x;

    for (int lin = tid; lin < 2048; lin += 256)
        ws2[lin] = w_out[(size_t)(c0 + (lin >> 7)) * 128 + (lin & 127)];
    for (int idx = tid; idx < 4096; idx += 256) {
        int h = idx >> 10, de = idx & 1023;
        ctxs[h * 1056 + (de >> 5) * 33 + (de & 31)] = g_ctx[b * 4224 + idx];
    }
    if (tid < 128) Ss[tid] = 1.0f / g_ctx[b * 4224 + 4096 + tid];
    __syncthreads();

    for (int oidx = tid; oidx < 1024; oidx += 256) {
        int cl = oidx >> 6, cpp = oidx & 63;
        int ch0 = cpp * 2;
        int h = ch0 >> 5, d = ch0 & 31;
        const float* cr0 = &ctxs[h * 1056 + d * 33];
        const float* cr1 = cr0 + 33;
        const float* wr  = &ws2[cl * 128 + h * 32];
        float a0 = 0.f, a1 = 0.f;
#pragma unroll
        for (int e = 0; e < 32; e++) {
            a0 = fmaf(wr[e], cr0[e], a0);
            a1 = fmaf(wr[e], cr1[e], a1);
        }
        uint32_t hi, lo;
        split_pair(a0 * Ss[ch0], a1 * Ss[ch0 + 1], hi, lo);
        uint32_t dst = (uint32_t)b * 8192 + (toff(c0 + cl, ch0) >> 2);
        g_W2hi[dst] = hi;
        g_W2lo[dst] = lo;
    }
}

// =============================================================================
// K3: y = W2_b @ q + b_out via mma.sync bf16-split, LayerNorm over C fused.
// 64 positions per block, 2 CTAs/SM; all tile loads are straight uint4 copies.
// smem: W2 hi/lo 64K | q hi/lo 32K | red 2K | stats 0.5K = 100,864 B
// =============================================================================
#define K3_WHI 0
#define K3_WLO 32768
#define K3_QHI 65536
#define K3_QLO 81920
#define K3_RS  98304
#define K3_RQ  99328
#define K3_MU  100352
#define K3_RST 100608

__global__ __launch_bounds__(256, 2)
void k_out(const float* __restrict__ b_out, const float* __restrict__ ln_g,
           const float* __restrict__ ln_b, float* __restrict__ out)
{
    extern __shared__ char smc[];
    const uint32_t sb = smem_u32(smc);
    float* red_s = (float*)(smc + K3_RS);    // [4][64]
    float* red_q = (float*)(smc + K3_RQ);    // [4][64]
    float* mu_s  = (float*)(smc + K3_MU);    // [64]
    float* rs_s  = (float*)(smc + K3_RST);   // [64]

    const int tid = threadIdx.x;
    const int warp = tid >> 5, lane = tid & 31;
    const int wm = warp & 3, wn = warp >> 2;          // wn in {0,1}
    const int b    = blockIdx.x >> 8;
    const int tile = blockIdx.x & 255;
    const int n0   = tile << 6;
    const size_t qt = (size_t)(b * 256 + tile) * 1024;  // uint4 base of q tile

#pragma unroll
    for (int i = 0; i < 8; i++) {
        int lin = tid + i * 256;              // 2048 uint4: W2 tiles
        ((uint4*)(smc + K3_WHI))[lin] = ((const uint4*)g_W2hi)[(size_t)b * 2048 + lin];
        ((uint4*)(smc + K3_WLO))[lin] = ((const uint4*)g_W2lo)[(size_t)b * 2048 + lin];
    }
#pragma unroll
    for (int i = 0; i < 4; i++) {
        int lin = tid + i * 256;              // 1024 uint4: q tiles
        ((uint4*)(smc + K3_QHI))[lin] = ((const uint4*)g_qhi)[qt + lin];
        ((uint4*)(smc + K3_QLO))[lin] = ((const uint4*)g_qlo)[qt + lin];
    }
    __syncthreads();

    const int l7 = lane & 7, lb3 = (lane >> 3) & 1, lb4 = (lane >> 4) & 1;
    float acc[2][4][4];
#pragma unroll
    for (int mt = 0; mt < 2; mt++)
#pragma unroll
        for (int u = 0; u < 4; u++)
#pragma unroll
            for (int r = 0; r < 4; r++) acc[mt][u][r] = 0.f;

    const int PA[3] = {K3_WHI, K3_WHI, K3_WLO};
    const int PB[3] = {K3_QHI, K3_QLO, K3_QHI};
#pragma unroll
    for (int ps = 0; ps < 3; ps++) {
        const uint32_t aB = sb + PA[ps], bB = sb + PB[ps];
#pragma unroll
        for (int k = 0; k < 8; k++) {
            uint32_t a[2][4];
#pragma unroll
            for (int mt = 0; mt < 2; mt++)
                ldsm4(a[mt], aB + toff(wm * 32 + mt * 16 + l7 + lb3 * 8, k * 16 + lb4 * 8));
            uint32_t bfr[2][4];
#pragma unroll
            for (int nt = 0; nt < 2; nt++)
                ldsm4(bfr[nt], bB + toff(wn * 32 + nt * 16 + l7 + lb4 * 8, k * 16 + lb3 * 8));
#pragma unroll
            for (int mt = 0; mt < 2; mt++)
#pragma unroll
                for (int u = 0; u < 4; u++)
                    mma16816(acc[mt][u], a[mt], bfr[u >> 1][(u & 1) * 2], bfr[u >> 1][(u & 1) * 2 + 1]);
        }
    }

    // bias
#pragma unroll
    for (int mt = 0; mt < 2; mt++)
#pragma unroll
        for (int h8 = 0; h8 < 2; h8++) {
            const float bo = b_out[wm * 32 + mt * 16 + h8 * 8 + (lane >> 2)];
#pragma unroll
            for (int u = 0; u < 4; u++) {
                acc[mt][u][h8 * 2]     += bo;
                acc[mt][u][h8 * 2 + 1] += bo;
            }
        }

    // LN partials
#pragma unroll
    for (int u = 0; u < 4; u++)
#pragma unroll
        for (int j = 0; j < 2; j++) {
            float a0 = acc[0][u][j],     a1 = acc[0][u][2 + j];
            float a2 = acc[1][u][j],     a3 = acc[1][u][2 + j];
            float s = a0 + a1 + a2 + a3;
            float q = a0 * a0 + a1 * a1 + a2 * a2 + a3 * a3;
            s += __shfl_xor_sync(0xffffffffu, s, 4);
            q += __shfl_xor_sync(0xffffffffu, q, 4);
            s += __shfl_xor_sync(0xffffffffu, s, 8);
            q += __shfl_xor_sync(0xffffffffu, q, 8);
            s += __shfl_xor_sync(0xffffffffu, s, 16);
            q += __shfl_xor_sync(0xffffffffu, q, 16);
            if ((lane >> 2) == 0) {
                int col = wn * 32 + u * 8 + (lane & 3) * 2 + j;
                red_s[wm * 64 + col] = s;
                red_q[wm * 64 + col] = q;
            }
        }
    __syncthreads();

    if (tid < 64) {
        float s = red_s[tid] + red_s[64 + tid] + red_s[128 + tid] + red_s[192 + tid];
        float q = red_q[tid] + red_q[64 + tid] + red_q[128 + tid] + red_q[192 + tid];
        float mu  = s * (1.0f / 128.0f);
        float var = q * (1.0f / 128.0f) - mu * mu;
        mu_s[tid] = mu;
        rs_s[tid] = rsqrtf(var + 1e-5f);
    }
    __syncthreads();

#pragma unroll
    for (int mt = 0; mt < 2; mt++)
#pragma unroll
        for (int h8 = 0; h8 < 2; h8++) {
            const int c = wm * 32 + mt * 16 + h8 * 8 + (lane >> 2);
            const float g  = ln_g[c];
            const float bb = ln_b[c];
            float* rowp = out + ((size_t)b * NCH + c) * NPOS + n0 + wn * 32 + (lane & 3) * 2;
#pragma unroll
            for (int u = 0; u < 4; u++) {
                int col = wn * 32 + u * 8 + (lane & 3) * 2;
                float v0 = (acc[mt][u][h8 * 2]     - mu_s[col])     * rs_s[col]     * g + bb;
                float v1 = (acc[mt][u][h8 * 2 + 1] - mu_s[col + 1]) * rs_s[col + 1] * g + bb;
                *(float2*)(rowp + u * 8) = make_float2(v0, v1);
            }
        }
}

// =============================================================================
extern "C" void kernel_launch(void* const* d_in, const int* in_sizes, int n_in,
                              void* d_out, int out_size)
{
    const float* x     = (const float*)d_in[0];
    const float* w_qkv = (const float*)d_in[1];
    const float* w_out = (const float*)d_in[2];
    const float* b_out = (const float*)d_in[3];
    const float* ln_g  = (const float*)d_in[4];
    const float* ln_b  = (const float*)d_in[5];
    float* out = (float*)d_out;

    cudaFuncSetAttribute(k_qkv, cudaFuncAttributeMaxDynamicSharedMemorySize,  98304);
    cudaFuncSetAttribute(k_ctx, cudaFuncAttributeMaxDynamicSharedMemorySize, 106496);
    cudaFuncSetAttribute(k_out, cudaFuncAttributeMaxDynamicSharedMemorySize, 100864);

    k_prep<<<96, 256>>>(w_qkv);
    k_qkv<<<4096, 256, 98304>>>(x);
    k_ctx<<<512, 256, 106496>>>();
    k_red<<<528, 128>>>();
    k_w2<<<128, 256>>>(w_out);
    k_out<<<4096, 256, 100864>>>(b_out, ln_g, ln_b, out);
}

// round 9
// speedup vs baseline: 1.3770x; 1.2497x over previous
#include <cuda_runtime.h>
#include <cuda_bf16.h>
#include <math.h>
#include <stdint.h>

#define NPOS 16384          // H*W
#define NB   16             // batch
#define NCH  128            // C == hidden
#define NTILE (NB * NPOS / 64)   // 4096 64-row tiles

// ---------------- device scratch (allocation-free rule: __device__ globals) ----
// q stored as swizzled 64x128 bf16 tiles: [tile][4096 u32]
__device__ uint32_t g_qhi [NTILE * 4096];
__device__ uint32_t g_qlo [NTILE * 4096];
__device__ float    g_part[NTILE * 4224];        // per 64-pos block: 4x1024 ctx + 128 se
__device__ float    g_ctx [NB * 4224];           // reduced per batch
// W2 stored as swizzled 128x128 bf16 tiles per b: [b][8192 u32]
__device__ uint32_t g_W2hi[NB * 8192];
__device__ uint32_t g_W2lo[NB * 8192];
// w_qkv pre-split + pre-swizzled: 3 chunks of 128x128
__device__ uint32_t g_wswh[3 * 8192];
__device__ uint32_t g_wswl[3 * 8192];

// ---------------- helpers -------------------------------------------------------
__device__ __forceinline__ uint32_t smem_u32(const void* p) {
    uint32_t a;
    asm("{ .reg .u64 t; cvta.to.shared.u64 t, %1; cvt.u32.u64 %0, t; }" : "=r"(a) : "l"(p));
    return a;
}
// swizzled byte offset within a 128-col bf16 tile (256B rows)
__device__ __forceinline__ uint32_t toff(int r, int c) {
    return (uint32_t)(r * 256 + (((c >> 3) ^ (r & 7)) << 4) + ((c & 7) << 1));
}
// swizzled byte offset within a 64-col bf16 tile (128B rows)
__device__ __forceinline__ uint32_t toff64(int r, int c) {
    return (uint32_t)(r * 128 + (((c >> 3) ^ (r & 7)) << 4) + ((c & 7) << 1));
}
__device__ __forceinline__ void ldsm4(uint32_t* r, uint32_t a) {
    asm volatile("ldmatrix.sync.aligned.m8n8.x4.shared.b16 {%0,%1,%2,%3}, [%4];"
                 : "=r"(r[0]), "=r"(r[1]), "=r"(r[2]), "=r"(r[3]) : "r"(a));
}
__device__ __forceinline__ void ldsm4t(uint32_t* r, uint32_t a) {
    asm volatile("ldmatrix.sync.aligned.m8n8.x4.trans.shared.b16 {%0,%1,%2,%3}, [%4];"
                 : "=r"(r[0]), "=r"(r[1]), "=r"(r[2]), "=r"(r[3]) : "r"(a));
}
__device__ __forceinline__ void mma16816(float* d, const uint32_t* a, uint32_t b0, uint32_t b1) {
    asm volatile(
        "mma.sync.aligned.m16n8k16.row.col.f32.bf16.bf16.f32 "
        "{%0,%1,%2,%3}, {%4,%5,%6,%7}, {%8,%9}, {%0,%1,%2,%3};"
        : "+f"(d[0]), "+f"(d[1]), "+f"(d[2]), "+f"(d[3])
        : "r"(a[0]), "r"(a[1]), "r"(a[2]), "r"(a[3]), "r"(b0), "r"(b1));
}
__device__ __forceinline__ void split_pair(float v0, float v1, uint32_t& hi, uint32_t& lo) {
    __nv_bfloat162 h = __float22bfloat162_rn(make_float2(v0, v1));
    float2 hf = __bfloat1622float2(h);
    __nv_bfloat162 l = __float22bfloat162_rn(make_float2(v0 - hf.x, v1 - hf.y));
    hi = *(uint32_t*)&h;
    lo = *(uint32_t*)&l;
}

// =============================================================================
// K0: pre-split + pre-swizzle w_qkv into 3 chunks of 128x128 bf16 tiles
// =============================================================================
__global__ __launch_bounds__(256)
void k_prep(const float* __restrict__ w_qkv)
{
    int idx = blockIdx.x * 256 + threadIdx.x;   // 24576 items
    int chunk = idx >> 13, rem = idx & 8191;
    int o = rem >> 6, cp = rem & 63;
    int c0 = cp * 2;
    float v0 = w_qkv[(size_t)(chunk * 128 + o) * NCH + c0];
    float v1 = w_qkv[(size_t)(chunk * 128 + o) * NCH + c0 + 1];
    uint32_t hi, lo;
    split_pair(v0, v1, hi, lo);
    uint32_t d = (uint32_t)chunk * 8192 + (toff(o, c0) >> 2);
    g_wswh[d] = hi;
    g_wswl[d] = lo;
}

// =============================================================================
// K1: fused qkv-GEMM + q-softmax + per-block ctx partial.
// 64 positions/block, 4096 blocks, 2 CTAs/SM.
// smem layout (97 KB peak):
//   X  [0,32K)   : x hi/lo (16K each)           -> reused for v hi/lo
//   W  [32K,64K) : one w component (hi OR lo)    -> reused for ctx red staging
//   EK [64K,96K) : ek hi/lo (16K each)
//   SE [96K,97K) : per-warp sumexp partials [8][32]
// =============================================================================
#define Q_XHI 0
#define Q_XLO 16384
#define Q_W   32768
#define Q_EKH 65536
#define Q_EKL 81920
#define Q_SE  98304
#define Q_SMEM 99328

__global__ __launch_bounds__(256, 2)
void k_qkv(const float* __restrict__ x)
{
    extern __shared__ char smc[];
    const uint32_t sb = smem_u32(smc);
    const int tid = threadIdx.x;
    const int warp = tid >> 5, lane = tid & 31;
    const int wm = warp & 1, wn = warp >> 1;        // wm: 2x32 pos, wn: 4x32 ch

    const int b    = blockIdx.x >> 8;
    const int tile = blockIdx.x & 255;
    const int n0   = tile << 6;
    const uint32_t gt = (uint32_t)blockIdx.x;        // global tile index

    // ---- load x tile [c=128 rows][p=64 cols], split bf16, toff64 swizzle ----
    {
        const float* xb = x + (size_t)b * NCH * NPOS + n0;
#pragma unroll
        for (int i = 0; i < 8; i++) {
            int lin = tid + i * 256;            // 2048 float4
            int c = lin >> 4, pq = lin & 15;
            float4 v = *(const float4*)(xb + (size_t)c * NPOS + pq * 4);
            uint32_t h01, l01, h23, l23;
            split_pair(v.x, v.y, h01, l01);
            split_pair(v.z, v.w, h23, l23);
            uint32_t o = toff64(c, pq * 4);
            *(uint32_t*)(smc + Q_XHI + o)     = h01;
            *(uint32_t*)(smc + Q_XHI + o + 4) = h23;
            *(uint32_t*)(smc + Q_XLO + o)     = l01;
            *(uint32_t*)(smc + Q_XLO + o + 4) = l23;
        }
    }

    const int l7 = lane & 7, lb3 = (lane >> 3) & 1, lb4 = (lane >> 4) & 1;
    const float scale = 0.17677669529663687f;   // 32^-0.5

    for (int chunk = 0; chunk < 3; chunk++) {
        // load w_hi(chunk)
        __syncthreads();
#pragma unroll
        for (int i = 0; i < 8; i++) {
            int lin = tid + i * 256;            // 2048 uint4
            ((uint4*)(smc + Q_W))[lin] = ((const uint4*)g_wswh)[chunk * 2048 + lin];
        }
        __syncthreads();

        float acc[2][4][4];
#pragma unroll
        for (int mt = 0; mt < 2; mt++)
#pragma unroll
            for (int u = 0; u < 4; u++)
#pragma unroll
                for (int r = 0; r < 4; r++) acc[mt][u][r] = 0.f;

        // pass 1: x_hi * w_hi ; pass 2: x_lo * w_hi
#pragma unroll
        for (int ps = 0; ps < 2; ps++) {
            const uint32_t aB = sb + (ps == 0 ? Q_XHI : Q_XLO);
#pragma unroll
            for (int k = 0; k < 8; k++) {
                uint32_t a[2][4];
#pragma unroll
                for (int mt = 0; mt < 2; mt++)
                    ldsm4t(a[mt], aB + toff64(k * 16 + l7 + lb4 * 8, wm * 32 + mt * 16 + lb3 * 8));
                uint32_t bfr[2][4];
#pragma unroll
                for (int nt = 0; nt < 2; nt++)
                    ldsm4(bfr[nt], sb + Q_W + toff(wn * 32 + nt * 16 + l7 + lb4 * 8, k * 16 + lb3 * 8));
#pragma unroll
                for (int mt = 0; mt < 2; mt++)
#pragma unroll
                    for (int u = 0; u < 4; u++)
                        mma16816(acc[mt][u], a[mt], bfr[u >> 1][(u & 1) * 2],
                                 bfr[u >> 1][(u & 1) * 2 + 1]);
            }
        }
        // swap in w_lo(chunk)
        __syncthreads();
#pragma unroll
        for (int i = 0; i < 8; i++) {
            int lin = tid + i * 256;
            ((uint4*)(smc + Q_W))[lin] = ((const uint4*)g_wswl)[chunk * 2048 + lin];
        }
        __syncthreads();
        // pass 3: x_hi * w_lo
#pragma unroll
        for (int k = 0; k < 8; k++) {
            uint32_t a[2][4];
#pragma unroll
            for (int mt = 0; mt < 2; mt++)
                ldsm4t(a[mt], sb + Q_XHI + toff64(k * 16 + l7 + lb4 * 8, wm * 32 + mt * 16 + lb3 * 8));
            uint32_t bfr[2][4];
#pragma unroll
            for (int nt = 0; nt < 2; nt++)
                ldsm4(bfr[nt], sb + Q_W + toff(wn * 32 + nt * 16 + l7 + lb4 * 8, k * 16 + lb3 * 8));
#pragma unroll
            for (int mt = 0; mt < 2; mt++)
#pragma unroll
                for (int u = 0; u < 4; u++)
                    mma16816(acc[mt][u], a[mt], bfr[u >> 1][(u & 1) * 2],
                             bfr[u >> 1][(u & 1) * 2 + 1]);
        }

        // ---- epilogues ----
        if (chunk == 0) {
            // q: softmax over 32 channels per head -> global swizzled tiles
#pragma unroll
            for (int mt = 0; mt < 2; mt++)
#pragma unroll
            for (int h8 = 0; h8 < 2; h8++) {
                float e[4][2];
                float s = 0.f;
#pragma unroll
                for (int u = 0; u < 4; u++)
#pragma unroll
                    for (int j = 0; j < 2; j++) {
                        float v = __expf(acc[mt][u][h8 * 2 + j]);
                        e[u][j] = v;
                        s += v;
                    }
                s += __shfl_xor_sync(0xffffffffu, s, 1);
                s += __shfl_xor_sync(0xffffffffu, s, 2);
                const float inv = scale / s;
                const int p = wm * 32 + mt * 16 + h8 * 8 + (lane >> 2);
#pragma unroll
                for (int u = 0; u < 4; u++) {
                    uint32_t hi, lo;
                    split_pair(e[u][0] * inv, e[u][1] * inv, hi, lo);
                    int ch0 = wn * 32 + u * 8 + (lane & 3) * 2;
                    uint32_t d = gt * 4096 + (toff(p, ch0) >> 2);
                    g_qhi[d] = hi;
                    g_qlo[d] = lo;
                }
            }
        } else if (chunk == 1) {
            // ek = exp(k): stage split into EK smem tile; sumexp partials
            float sep[4][2];
#pragma unroll
            for (int u = 0; u < 4; u++) { sep[u][0] = 0.f; sep[u][1] = 0.f; }
#pragma unroll
            for (int mt = 0; mt < 2; mt++)
#pragma unroll
            for (int h8 = 0; h8 < 2; h8++) {
                const int p = wm * 32 + mt * 16 + h8 * 8 + (lane >> 2);
#pragma unroll
                for (int u = 0; u < 4; u++) {
                    float v0 = __expf(acc[mt][u][h8 * 2]);
                    float v1 = __expf(acc[mt][u][h8 * 2 + 1]);
                    sep[u][0] += v0; sep[u][1] += v1;
                    uint32_t hi, lo;
                    split_pair(v0, v1, hi, lo);
                    int ch0 = wn * 32 + u * 8 + (lane & 3) * 2;
                    uint32_t o = toff(p, ch0);
                    *(uint32_t*)(smc + Q_EKH + o) = hi;
                    *(uint32_t*)(smc + Q_EKL + o) = lo;
                }
            }
            // reduce sumexp over the warp's 32 rows
            float* se = (float*)(smc + Q_SE);
#pragma unroll
            for (int u = 0; u < 4; u++)
#pragma unroll
                for (int j = 0; j < 2; j++) {
                    float s = sep[u][j];
                    s += __shfl_xor_sync(0xffffffffu, s, 4);
                    s += __shfl_xor_sync(0xffffffffu, s, 8);
                    s += __shfl_xor_sync(0xffffffffu, s, 16);
                    if ((lane >> 2) == 0)
                        se[warp * 32 + u * 8 + (lane & 3) * 2 + j] = s;
                }
        } else {
            // v: stage split into X smem buffers (x no longer needed)
            __syncthreads();   // all warps done reading x
#pragma unroll
            for (int mt = 0; mt < 2; mt++)
#pragma unroll
            for (int h8 = 0; h8 < 2; h8++) {
                const int p = wm * 32 + mt * 16 + h8 * 8 + (lane >> 2);
#pragma unroll
                for (int u = 0; u < 4; u++) {
                    uint32_t hi, lo;
                    split_pair(acc[mt][u][h8 * 2], acc[mt][u][h8 * 2 + 1], hi, lo);
                    int ch0 = wn * 32 + u * 8 + (lane & 3) * 2;
                    uint32_t o = toff(p, ch0);
                    *(uint32_t*)(smc + Q_XHI + o) = hi;
                    *(uint32_t*)(smc + Q_XLO + o) = lo;
                }
            }
        }
    }
    __syncthreads();   // EK + V tiles ready

    // ---- ctx partial: ctx_h[d][e] = sum_p ek[p,d] v[p,e]  (3 split passes) ----
    {
        const int h = warp & 3, ks = warp >> 2;
        float ctx[2][4][4];
#pragma unroll
        for (int mt = 0; mt < 2; mt++)
#pragma unroll
            for (int u = 0; u < 4; u++)
#pragma unroll
                for (int r = 0; r < 4; r++) ctx[mt][u][r] = 0.f;

        const int PA[3] = {Q_EKH, Q_EKH, Q_EKL};
        const int PB[3] = {Q_XHI, Q_XLO, Q_XHI};
#pragma unroll
        for (int ps = 0; ps < 3; ps++) {
            const uint32_t aB = sb + PA[ps], bB = sb + PB[ps];
#pragma unroll
            for (int kk = 0; kk < 2; kk++) {
                const int p0 = ks * 32 + kk * 16;
                uint32_t a[2][4];
#pragma unroll
                for (int mt = 0; mt < 2; mt++)
                    ldsm4t(a[mt], aB + toff(p0 + l7 + lb4 * 8, h * 32 + mt * 16 + lb3 * 8));
                uint32_t bfr[2][4];
#pragma unroll
                for (int nt = 0; nt < 2; nt++)
                    ldsm4t(bfr[nt], bB + toff(p0 + l7 + lb3 * 8, h * 32 + nt * 16 + lb4 * 8));
#pragma unroll
                for (int mt = 0; mt < 2; mt++)
#pragma unroll
                    for (int u = 0; u < 4; u++)
                        mma16816(ctx[mt][u], a[mt], bfr[u >> 1][(u & 1) * 2],
                                 bfr[u >> 1][(u & 1) * 2 + 1]);
            }
        }

        // stage per-warp ctx fragments into red buffer (aliases Q_W)
        float* rb = (float*)(smc + Q_W) + ks * 4096 + h * 1024;
#pragma unroll
        for (int mt = 0; mt < 2; mt++)
#pragma unroll
            for (int u = 0; u < 4; u++) {
                int dr = mt * 16 + (lane >> 2), e = u * 8 + (lane & 3) * 2;
                rb[dr * 32 + e]           = ctx[mt][u][0];
                rb[dr * 32 + e + 1]       = ctx[mt][u][1];
                rb[(dr + 8) * 32 + e]     = ctx[mt][u][2];
                rb[(dr + 8) * 32 + e + 1] = ctx[mt][u][3];
            }
    }
    __syncthreads();

    // ---- write block partial: 4096 ctx + 128 sumexp ----
    {
        const size_t pbase = (size_t)gt * 4224;
        const float* r0 = (const float*)(smc + Q_W);
        for (int idx = tid; idx < 4096; idx += 256)
            g_part[pbase + idx] = r0[idx] + r0[4096 + idx];
        if (tid < 128) {
            const float* se = (const float*)(smc + Q_SE);
            int wq = tid >> 5;   // = wn of the channel
            g_part[pbase + 4096 + tid] =
                se[(wq * 2) * 32 + (tid & 31)] + se[(wq * 2 + 1) * 32 + (tid & 31)];
        }
    }
}

// =============================================================================
// K2: reduce 256 block partials per batch -> g_ctx[b][4224]
// =============================================================================
__global__ __launch_bounds__(128, 8)
void k_red()
{
    const int b = blockIdx.x / 33, sc = blockIdx.x % 33;
    const int slot = sc * 128 + threadIdx.x;
    const float* src = g_part + (size_t)b * 256 * 4224 + slot;
    float s = 0.f;
#pragma unroll 4
    for (int t = 0; t < 256; t++) s += src[(size_t)t * 4224];
    g_ctx[b * 4224 + slot] = s;
}

// =============================================================================
// K3: normalize ctx, build fused W2, write as swizzled bf16 tiles per b.
// =============================================================================
__global__ __launch_bounds__(256, 4)
void k_w2(const float* __restrict__ w_out)
{
    __shared__ float ctxs[4224];     // [h][d][33]
    __shared__ float Ss[128];
    __shared__ float ws2[2048];      // 16 c-rows x 128 ch

    const int b  = blockIdx.x >> 3;
    const int c0 = (blockIdx.x & 7) * 16;
    const int tid = threadIdx.x;

    for (int lin = tid; lin < 2048; lin += 256)
        ws2[lin] = w_out[(size_t)(c0 + (lin >> 7)) * 128 + (lin & 127)];
    for (int idx = tid; idx < 4096; idx += 256) {
        int h = idx >> 10, de = idx & 1023;
        ctxs[h * 1056 + (de >> 5) * 33 + (de & 31)] = g_ctx[b * 4224 + idx];
    }
    if (tid < 128) Ss[tid] = 1.0f / g_ctx[b * 4224 + 4096 + tid];
    __syncthreads();

    for (int oidx = tid; oidx < 1024; oidx += 256) {
        int cl = oidx >> 6, cpp = oidx & 63;
        int ch0 = cpp * 2;
        int h = ch0 >> 5, d = ch0 & 31;
        const float* cr0 = &ctxs[h * 1056 + d * 33];
        const float* cr1 = cr0 + 33;
        const float* wr  = &ws2[cl * 128 + h * 32];
        float a0 = 0.f, a1 = 0.f;
#pragma unroll
        for (int e = 0; e < 32; e++) {
            a0 = fmaf(wr[e], cr0[e], a0);
            a1 = fmaf(wr[e], cr1[e], a1);
        }
        uint32_t hi, lo;
        split_pair(a0 * Ss[ch0], a1 * Ss[ch0 + 1], hi, lo);
        uint32_t dst = (uint32_t)b * 8192 + (toff(c0 + cl, ch0) >> 2);
        g_W2hi[dst] = hi;
        g_W2lo[dst] = lo;
    }
}

// =============================================================================
// K4: y = W2_b @ q + b_out via mma.sync bf16-split, LayerNorm over C fused.
// 64 positions per block, 2 CTAs/SM; tile loads are straight uint4 copies.
// =============================================================================
#define K3_WHI 0
#define K3_WLO 32768
#define K3_QHI 65536
#define K3_QLO 81920
#define K3_RS  98304
#define K3_RQ  99328
#define K3_MU  100352
#define K3_RST 100608

__global__ __launch_bounds__(256, 2)
void k_out(const float* __restrict__ b_out, const float* __restrict__ ln_g,
           const float* __restrict__ ln_b, float* __restrict__ out)
{
    extern __shared__ char smc[];
    const uint32_t sb = smem_u32(smc);
    float* red_s = (float*)(smc + K3_RS);    // [4][64]
    float* red_q = (float*)(smc + K3_RQ);    // [4][64]
    float* mu_s  = (float*)(smc + K3_MU);    // [64]
    float* rs_s  = (float*)(smc + K3_RST);   // [64]

    const int tid = threadIdx.x;
    const int warp = tid >> 5, lane = tid & 31;
    const int wm = warp & 3, wn = warp >> 2;          // wn in {0,1}
    const int b    = blockIdx.x >> 8;
    const int tile = blockIdx.x & 255;
    const int n0   = tile << 6;
    const size_t qt = (size_t)blockIdx.x * 1024;      // uint4 base of q tile

#pragma unroll
    for (int i = 0; i < 8; i++) {
        int lin = tid + i * 256;              // 2048 uint4: W2 tiles
        ((uint4*)(smc + K3_WHI))[lin] = ((const uint4*)g_W2hi)[(size_t)b * 2048 + lin];
        ((uint4*)(smc + K3_WLO))[lin] = ((const uint4*)g_W2lo)[(size_t)b * 2048 + lin];
    }
#pragma unroll
    for (int i = 0; i < 4; i++) {
        int lin = tid + i * 256;              // 1024 uint4: q tiles
        ((uint4*)(smc + K3_QHI))[lin] = ((const uint4*)g_qhi)[qt + lin];
        ((uint4*)(smc + K3_QLO))[lin] = ((const uint4*)g_qlo)[qt + lin];
    }
    __syncthreads();

    const int l7 = lane & 7, lb3 = (lane >> 3) & 1, lb4 = (lane >> 4) & 1;
    float acc[2][4][4];
#pragma unroll
    for (int mt = 0; mt < 2; mt++)
#pragma unroll
        for (int u = 0; u < 4; u++)
#pragma unroll
            for (int r = 0; r < 4; r++) acc[mt][u][r] = 0.f;

    const int PA[3] = {K3_WHI, K3_WHI, K3_WLO};
    const int PB[3] = {K3_QHI, K3_QLO, K3_QHI};
#pragma unroll
    for (int ps = 0; ps < 3; ps++) {
        const uint32_t aB = sb + PA[ps], bB = sb + PB[ps];
#pragma unroll
        for (int k = 0; k < 8; k++) {
            uint32_t a[2][4];
#pragma unroll
            for (int mt = 0; mt < 2; mt++)
                ldsm4(a[mt], aB + toff(wm * 32 + mt * 16 + l7 + lb3 * 8, k * 16 + lb4 * 8));
            uint32_t bfr[2][4];
#pragma unroll
            for (int nt = 0; nt < 2; nt++)
                ldsm4(bfr[nt], bB + toff(wn * 32 + nt * 16 + l7 + lb4 * 8, k * 16 + lb3 * 8));
#pragma unroll
            for (int mt = 0; mt < 2; mt++)
#pragma unroll
                for (int u = 0; u < 4; u++)
                    mma16816(acc[mt][u], a[mt], bfr[u >> 1][(u & 1) * 2], bfr[u >> 1][(u & 1) * 2 + 1]);
        }
    }

    // bias
#pragma unroll
    for (int mt = 0; mt < 2; mt++)
#pragma unroll
        for (int h8 = 0; h8 < 2; h8++) {
            const float bo = b_out[wm * 32 + mt * 16 + h8 * 8 + (lane >> 2)];
#pragma unroll
            for (int u = 0; u < 4; u++) {
                acc[mt][u][h8 * 2]     += bo;
                acc[mt][u][h8 * 2 + 1] += bo;
            }
        }

    // LN partials
#pragma unroll
    for (int u = 0; u < 4; u++)
#pragma unroll
        for (int j = 0; j < 2; j++) {
            float a0 = acc[0][u][j],     a1 = acc[0][u][2 + j];
            float a2 = acc[1][u][j],     a3 = acc[1][u][2 + j];
            float s = a0 + a1 + a2 + a3;
            float q = a0 * a0 + a1 * a1 + a2 * a2 + a3 * a3;
            s += __shfl_xor_sync(0xffffffffu, s, 4);
            q += __shfl_xor_sync(0xffffffffu, q, 4);
            s += __shfl_xor_sync(0xffffffffu, s, 8);
            q += __shfl_xor_sync(0xffffffffu, q, 8);
            s += __shfl_xor_sync(0xffffffffu, s, 16);
            q += __shfl_xor_sync(0xffffffffu, q, 16);
            if ((lane >> 2) == 0) {
                int col = wn * 32 + u * 8 + (lane & 3) * 2 + j;
                red_s[wm * 64 + col] = s;
                red_q[wm * 64 + col] = q;
            }
        }
    __syncthreads();

    if (tid < 64) {
        float s = red_s[tid] + red_s[64 + tid] + red_s[128 + tid] + red_s[192 + tid];
        float q = red_q[tid] + red_q[64 + tid] + red_q[128 + tid] + red_q[192 + tid];
        float mu  = s * (1.0f / 128.0f);
        float var = q * (1.0f / 128.0f) - mu * mu;
        mu_s[tid] = mu;
        rs_s[tid] = rsqrtf(var + 1e-5f);
    }
    __syncthreads();

#pragma unroll
    for (int mt = 0; mt < 2; mt++)
#pragma unroll
        for (int h8 = 0; h8 < 2; h8++) {
            const int c = wm * 32 + mt * 16 + h8 * 8 + (lane >> 2);
            const float g  = ln_g[c];
            const float bb = ln_b[c];
            float* rowp = out + ((size_t)b * NCH + c) * NPOS + n0 + wn * 32 + (lane & 3) * 2;
#pragma unroll
            for (int u = 0; u < 4; u++) {
                int col = wn * 32 + u * 8 + (lane & 3) * 2;
                float v0 = (acc[mt][u][h8 * 2]     - mu_s[col])     * rs_s[col]     * g + bb;
                float v1 = (acc[mt][u][h8 * 2 + 1] - mu_s[col + 1]) * rs_s[col + 1] * g + bb;
                *(float2*)(rowp + u * 8) = make_float2(v0, v1);
            }
        }
}

// =============================================================================
extern "C" void kernel_launch(void* const* d_in, const int* in_sizes, int n_in,
                              void* d_out, int out_size)
{
    const float* x     = (const float*)d_in[0];
    const float* w_qkv = (const float*)d_in[1];
    const float* w_out = (const float*)d_in[2];
    const float* b_out = (const float*)d_in[3];
    const float* ln_g  = (const float*)d_in[4];
    const float* ln_b  = (const float*)d_in[5];
    float* out = (float*)d_out;

    cudaFuncSetAttribute(k_qkv, cudaFuncAttributeMaxDynamicSharedMemorySize, Q_SMEM);
    cudaFuncSetAttribute(k_out, cudaFuncAttributeMaxDynamicSharedMemorySize, 100864);

    k_prep<<<96, 256>>>(w_qkv);
    k_qkv<<<4096, 256, Q_SMEM>>>(x);
    k_red<<<528, 128>>>();
    k_w2<<<128, 256>>>(w_out);
    k_out<<<4096, 256, 100864>>>(b_out, ln_g, ln_b, out);
}

// round 10
// speedup vs baseline: 2.4452x; 1.7757x over previous
#include <cuda_runtime.h>
#include <cuda_fp16.h>
#include <cuda_bf16.h>
#include <math.h>
#include <stdint.h>

#define NPOS 16384          // H*W
#define NB   16             // batch
#define NCH  128            // C == hidden
#define NTILE (NB * NPOS / 64)   // 4096 64-row tiles

// ---------------- device scratch (allocation-free rule: __device__ globals) ----
__device__ uint32_t g_q   [NTILE * 4096];   // q fp16 pairs, swizzled 64x128 tiles
__device__ uint32_t g_part[NTILE * 2176];   // per tile: 2048 bf16x2 ctx + 128 f32 se
__device__ float    g_ctx [NB * 4224];      // reduced per batch (4096 ctx + 128 se)
__device__ uint32_t g_W2  [NB * 8192];      // fused W2 fp16, swizzled 128x128 per b
__device__ uint32_t g_wsw [3 * 8192];       // w_qkv fp16, 3 swizzled 128x128 chunks

// ---------------- helpers -------------------------------------------------------
__device__ __forceinline__ uint32_t smem_u32(const void* p) {
    uint32_t a;
    asm("{ .reg .u64 t; cvta.to.shared.u64 t, %1; cvt.u32.u64 %0, t; }" : "=r"(a) : "l"(p));
    return a;
}
// swizzled byte offset within a 128-col b16 tile (256B rows)
__device__ __forceinline__ uint32_t toff(int r, int c) {
    return (uint32_t)(r * 256 + (((c >> 3) ^ (r & 7)) << 4) + ((c & 7) << 1));
}
// swizzled byte offset within a 64-col b16 tile (128B rows)
__device__ __forceinline__ uint32_t toff64(int r, int c) {
    return (uint32_t)(r * 128 + (((c >> 3) ^ (r & 7)) << 4) + ((c & 7) << 1));
}
__device__ __forceinline__ void ldsm4(uint32_t* r, uint32_t a) {
    asm volatile("ldmatrix.sync.aligned.m8n8.x4.shared.b16 {%0,%1,%2,%3}, [%4];"
                 : "=r"(r[0]), "=r"(r[1]), "=r"(r[2]), "=r"(r[3]) : "r"(a));
}
__device__ __forceinline__ void ldsm4t(uint32_t* r, uint32_t a) {
    asm volatile("ldmatrix.sync.aligned.m8n8.x4.trans.shared.b16 {%0,%1,%2,%3}, [%4];"
                 : "=r"(r[0]), "=r"(r[1]), "=r"(r[2]), "=r"(r[3]) : "r"(a));
}
__device__ __forceinline__ void mma16816(float* d, const uint32_t* a, uint32_t b0, uint32_t b1) {
    asm volatile(
        "mma.sync.aligned.m16n8k16.row.col.f32.f16.f16.f32 "
        "{%0,%1,%2,%3}, {%4,%5,%6,%7}, {%8,%9}, {%0,%1,%2,%3};"
        : "+f"(d[0]), "+f"(d[1]), "+f"(d[2]), "+f"(d[3])
        : "r"(a[0]), "r"(a[1]), "r"(a[2]), "r"(a[3]), "r"(b0), "r"(b1));
}
__device__ __forceinline__ uint32_t pack_h2(float a, float b) {
    __half2 h = __floats2half2_rn(a, b);
    return *(uint32_t*)&h;
}
__device__ __forceinline__ void split_h(float v0, float v1, uint32_t& hi, uint32_t& lo) {
    __half2 h = __floats2half2_rn(v0, v1);
    float2 hf = __half22float2(h);
    __half2 l = __floats2half2_rn(v0 - hf.x, v1 - hf.y);
    hi = *(uint32_t*)&h;
    lo = *(uint32_t*)&l;
}

// =============================================================================
// K0: convert w_qkv to fp16, pre-swizzled, 3 chunks of 128x128
// =============================================================================
__global__ __launch_bounds__(256)
void k_prep(const float* __restrict__ w_qkv)
{
    int idx = blockIdx.x * 256 + threadIdx.x;   // 24576 items
    int chunk = idx >> 13, rem = idx & 8191;
    int o = rem >> 6, cp = rem & 63;
    int c0 = cp * 2;
    float v0 = w_qkv[(size_t)(chunk * 128 + o) * NCH + c0];
    float v1 = w_qkv[(size_t)(chunk * 128 + o) * NCH + c0 + 1];
    g_wsw[(uint32_t)chunk * 8192 + (toff(o, c0) >> 2)] = pack_h2(v0, v1);
}

// =============================================================================
// K1: fused qkv-GEMM (fp16 single-pass) + q-softmax + ctx partial (split fp16).
// 64 positions/block, 4096 blocks, 2 CTAs/SM.
// smem: X 16K (x -> v_hi) | W 32K (w chunk -> ctx red staging) |
//       EKH 16K | EKL 16K | VL 16K | SE 1K  = 97 KB
// =============================================================================
#define Q_X   0
#define Q_W   16384
#define Q_EKH 49152
#define Q_EKL 65536
#define Q_VL  81920
#define Q_SE  98304
#define Q_SMEM 99328

__global__ __launch_bounds__(256, 2)
void k_qkv(const float* __restrict__ x)
{
    extern __shared__ char smc[];
    const uint32_t sb = smem_u32(smc);
    const int tid = threadIdx.x;
    const int warp = tid >> 5, lane = tid & 31;
    const int wm = warp & 1, wn = warp >> 1;        // wm: 2x32 pos, wn: 4x32 ch

    const int b    = blockIdx.x >> 8;
    const int tile = blockIdx.x & 255;
    const int n0   = tile << 6;
    const uint32_t gt = (uint32_t)blockIdx.x;

    // ---- load x tile [c=128][p=64] as fp16 (single), toff64 swizzle ----
    {
        const float* xb = x + (size_t)b * NCH * NPOS + n0;
#pragma unroll
        for (int i = 0; i < 8; i++) {
            int lin = tid + i * 256;            // 2048 float4
            int c = lin >> 4, pq = lin & 15;
            float4 v = *(const float4*)(xb + (size_t)c * NPOS + pq * 4);
            uint32_t o = toff64(c, pq * 4);
            *(uint32_t*)(smc + Q_X + o)     = pack_h2(v.x, v.y);
            *(uint32_t*)(smc + Q_X + o + 4) = pack_h2(v.z, v.w);
        }
    }

    const int l7 = lane & 7, lb3 = (lane >> 3) & 1, lb4 = (lane >> 4) & 1;
    const float scale = 0.17677669529663687f;   // 32^-0.5

    for (int chunk = 0; chunk < 3; chunk++) {
        __syncthreads();
        // copy w chunk (32 KB, pre-swizzled fp16)
#pragma unroll
        for (int i = 0; i < 8; i++) {
            int lin = tid + i * 256;            // 2048 uint4
            ((uint4*)(smc + Q_W))[lin] = ((const uint4*)g_wsw)[chunk * 2048 + lin];
        }
        __syncthreads();

        float acc[2][4][4];
#pragma unroll
        for (int mt = 0; mt < 2; mt++)
#pragma unroll
            for (int u = 0; u < 4; u++)
#pragma unroll
                for (int r = 0; r < 4; r++) acc[mt][u][r] = 0.f;

        // single fp16 pass
#pragma unroll
        for (int k = 0; k < 8; k++) {
            uint32_t a[2][4];
#pragma unroll
            for (int mt = 0; mt < 2; mt++)
                ldsm4t(a[mt], sb + Q_X + toff64(k * 16 + l7 + lb4 * 8, wm * 32 + mt * 16 + lb3 * 8));
            uint32_t bfr[2][4];
#pragma unroll
            for (int nt = 0; nt < 2; nt++)
                ldsm4(bfr[nt], sb + Q_W + toff(wn * 32 + nt * 16 + l7 + lb4 * 8, k * 16 + lb3 * 8));
#pragma unroll
            for (int mt = 0; mt < 2; mt++)
#pragma unroll
                for (int u = 0; u < 4; u++)
                    mma16816(acc[mt][u], a[mt], bfr[u >> 1][(u & 1) * 2],
                             bfr[u >> 1][(u & 1) * 2 + 1]);
        }

        // ---- epilogues ----
        if (chunk == 0) {
            // q: softmax over 32 channels per head -> global fp16 swizzled tiles
#pragma unroll
            for (int mt = 0; mt < 2; mt++)
#pragma unroll
            for (int h8 = 0; h8 < 2; h8++) {
                float e[4][2];
                float s = 0.f;
#pragma unroll
                for (int u = 0; u < 4; u++)
#pragma unroll
                    for (int j = 0; j < 2; j++) {
                        float v = __expf(acc[mt][u][h8 * 2 + j]);
                        e[u][j] = v;
                        s += v;
                    }
                s += __shfl_xor_sync(0xffffffffu, s, 1);
                s += __shfl_xor_sync(0xffffffffu, s, 2);
                const float inv = scale / s;
                const int p = wm * 32 + mt * 16 + h8 * 8 + (lane >> 2);
#pragma unroll
                for (int u = 0; u < 4; u++) {
                    int ch0 = wn * 32 + u * 8 + (lane & 3) * 2;
                    g_q[gt * 4096 + (toff(p, ch0) >> 2)] = pack_h2(e[u][0] * inv, e[u][1] * inv);
                }
            }
        } else if (chunk == 1) {
            // ek = exp(k): split fp16 into EKH/EKL; sumexp partials (f32 exact)
            float sep[4][2];
#pragma unroll
            for (int u = 0; u < 4; u++) { sep[u][0] = 0.f; sep[u][1] = 0.f; }
#pragma unroll
            for (int mt = 0; mt < 2; mt++)
#pragma unroll
            for (int h8 = 0; h8 < 2; h8++) {
                const int p = wm * 32 + mt * 16 + h8 * 8 + (lane >> 2);
#pragma unroll
                for (int u = 0; u < 4; u++) {
                    float v0 = __expf(acc[mt][u][h8 * 2]);
                    float v1 = __expf(acc[mt][u][h8 * 2 + 1]);
                    sep[u][0] += v0; sep[u][1] += v1;
                    uint32_t hi, lo;
                    split_h(v0, v1, hi, lo);
                    int ch0 = wn * 32 + u * 8 + (lane & 3) * 2;
                    uint32_t o = toff(p, ch0);
                    *(uint32_t*)(smc + Q_EKH + o) = hi;
                    *(uint32_t*)(smc + Q_EKL + o) = lo;
                }
            }
            float* se = (float*)(smc + Q_SE);
#pragma unroll
            for (int u = 0; u < 4; u++)
#pragma unroll
                for (int j = 0; j < 2; j++) {
                    float s = sep[u][j];
                    s += __shfl_xor_sync(0xffffffffu, s, 4);
                    s += __shfl_xor_sync(0xffffffffu, s, 8);
                    s += __shfl_xor_sync(0xffffffffu, s, 16);
                    if ((lane >> 2) == 0)
                        se[warp * 32 + u * 8 + (lane & 3) * 2 + j] = s;
                }
        } else {
            // v: split fp16 -> X (v_hi) + VL (v_lo); x no longer needed
            __syncthreads();   // all warps done reading x
#pragma unroll
            for (int mt = 0; mt < 2; mt++)
#pragma unroll
            for (int h8 = 0; h8 < 2; h8++) {
                const int p = wm * 32 + mt * 16 + h8 * 8 + (lane >> 2);
#pragma unroll
                for (int u = 0; u < 4; u++) {
                    uint32_t hi, lo;
                    split_h(acc[mt][u][h8 * 2], acc[mt][u][h8 * 2 + 1], hi, lo);
                    int ch0 = wn * 32 + u * 8 + (lane & 3) * 2;
                    uint32_t o = toff(p, ch0);
                    *(uint32_t*)(smc + Q_X + o)  = hi;
                    *(uint32_t*)(smc + Q_VL + o) = lo;
                }
            }
        }
    }
    __syncthreads();   // EK + V tiles ready

    // ---- ctx partial: ctx_h[d][e] = sum_p ek[p,d] v[p,e]  (3 split passes) ----
    const int h = warp & 3, ks = warp >> 2;
    float ctx[2][4][4];
#pragma unroll
    for (int mt = 0; mt < 2; mt++)
#pragma unroll
        for (int u = 0; u < 4; u++)
#pragma unroll
            for (int r = 0; r < 4; r++) ctx[mt][u][r] = 0.f;

    {
        const int PA[3] = {Q_EKH, Q_EKH, Q_EKL};
        const int PB[3] = {Q_X,   Q_VL,  Q_X};
#pragma unroll
        for (int ps = 0; ps < 3; ps++) {
            const uint32_t aB = sb + PA[ps], bB = sb + PB[ps];
#pragma unroll
            for (int kk = 0; kk < 2; kk++) {
                const int p0 = ks * 32 + kk * 16;
                uint32_t a[2][4];
#pragma unroll
                for (int mt = 0; mt < 2; mt++)
                    ldsm4t(a[mt], aB + toff(p0 + l7 + lb4 * 8, h * 32 + mt * 16 + lb3 * 8));
                uint32_t bfr[2][4];
#pragma unroll
                for (int nt = 0; nt < 2; nt++)
                    ldsm4t(bfr[nt], bB + toff(p0 + l7 + lb3 * 8, h * 32 + nt * 16 + lb4 * 8));
#pragma unroll
                for (int mt = 0; mt < 2; mt++)
#pragma unroll
                    for (int u = 0; u < 4; u++)
                        mma16816(ctx[mt][u], a[mt], bfr[u >> 1][(u & 1) * 2],
                                 bfr[u >> 1][(u & 1) * 2 + 1]);
            }
        }
    }

    // two-phase ctx staging into 16KB red buffer (aliases W)
    float* rb = (float*)(smc + Q_W);
    __syncthreads();   // all ldsm on EK/V done before W alias reuse is safe anyway
    if (ks == 0) {
#pragma unroll
        for (int mt = 0; mt < 2; mt++)
#pragma unroll
            for (int u = 0; u < 4; u++) {
                int dr = mt * 16 + (lane >> 2), e = u * 8 + (lane & 3) * 2;
                float* r = rb + h * 1024;
                r[dr * 32 + e]           = ctx[mt][u][0];
                r[dr * 32 + e + 1]       = ctx[mt][u][1];
                r[(dr + 8) * 32 + e]     = ctx[mt][u][2];
                r[(dr + 8) * 32 + e + 1] = ctx[mt][u][3];
            }
    }
    __syncthreads();
    if (ks == 1) {
#pragma unroll
        for (int mt = 0; mt < 2; mt++)
#pragma unroll
            for (int u = 0; u < 4; u++) {
                int dr = mt * 16 + (lane >> 2), e = u * 8 + (lane & 3) * 2;
                float* r = rb + h * 1024;
                r[dr * 32 + e]           += ctx[mt][u][0];
                r[dr * 32 + e + 1]       += ctx[mt][u][1];
                r[(dr + 8) * 32 + e]     += ctx[mt][u][2];
                r[(dr + 8) * 32 + e + 1] += ctx[mt][u][3];
            }
    }
    __syncthreads();

    // ---- write block partial: 2048 bf16x2 ctx + 128 f32 se ----
    {
        const size_t pbase = (size_t)gt * 2176;
#pragma unroll
        for (int i = 0; i < 8; i++) {
            int idx = tid + i * 256;            // 2048
            __nv_bfloat162 pkt = __float22bfloat162_rn(make_float2(rb[idx * 2], rb[idx * 2 + 1]));
            g_part[pbase + idx] = *(uint32_t*)&pkt;
        }
        if (tid < 128) {
            const float* se = (const float*)(smc + Q_SE);
            int wq = tid >> 5;
            float s = se[(wq * 2) * 32 + (tid & 31)] + se[(wq * 2 + 1) * 32 + (tid & 31)];
            g_part[pbase + 2048 + tid] = __float_as_uint(s);
        }
    }
}

// =============================================================================
// K2: reduce 256 tile partials per batch -> g_ctx[b][4224]
// =============================================================================
__global__ __launch_bounds__(128, 8)
void k_red()
{
    const int b = blockIdx.x / 17, g = blockIdx.x % 17;
    const int col = g * 128 + threadIdx.x;      // 0..2175
    const uint32_t* src = g_part + (size_t)b * 256 * 2176 + col;
    if (col < 2048) {
        float s0 = 0.f, s1 = 0.f;
#pragma unroll 4
        for (int t = 0; t < 256; t++) {
            uint32_t u = src[(size_t)t * 2176];
            float2 f = __bfloat1622float2(*(__nv_bfloat162*)&u);
            s0 += f.x; s1 += f.y;
        }
        g_ctx[b * 4224 + col * 2]     = s0;
        g_ctx[b * 4224 + col * 2 + 1] = s1;
    } else {
        float s = 0.f;
#pragma unroll 4
        for (int t = 0; t < 256; t++)
            s += __uint_as_float(src[(size_t)t * 2176]);
        g_ctx[b * 4224 + 4096 + (col - 2048)] = s;
    }
}

// =============================================================================
// K3: normalize ctx, build fused W2 (fp16 single), swizzled tiles per b.
// =============================================================================
__global__ __launch_bounds__(256, 4)
void k_w2(const float* __restrict__ w_out)
{
    __shared__ float ctxs[4224];     // [h][d][33]
    __shared__ float Ss[128];
    __shared__ float ws2[2048];      // 16 c-rows x 128 ch

    const int b  = blockIdx.x >> 3;
    const int c0 = (blockIdx.x & 7) * 16;
    const int tid = threadIdx.x;

    for (int lin = tid; lin < 2048; lin += 256)
        ws2[lin] = w_out[(size_t)(c0 + (lin >> 7)) * 128 + (lin & 127)];
    for (int idx = tid; idx < 4096; idx += 256) {
        int h = idx >> 10, de = idx & 1023;
        ctxs[h * 1056 + (de >> 5) * 33 + (de & 31)] = g_ctx[b * 4224 + idx];
    }
    if (tid < 128) Ss[tid] = 1.0f / g_ctx[b * 4224 + 4096 + tid];
    __syncthreads();

    for (int oidx = tid; oidx < 1024; oidx += 256) {
        int cl = oidx >> 6, cpp = oidx & 63;
        int ch0 = cpp * 2;
        int h = ch0 >> 5, d = ch0 & 31;
        const float* cr0 = &ctxs[h * 1056 + d * 33];
        const float* cr1 = cr0 + 33;
        const float* wr  = &ws2[cl * 128 + h * 32];
        float a0 = 0.f, a1 = 0.f;
#pragma unroll
        for (int e = 0; e < 32; e++) {
            a0 = fmaf(wr[e], cr0[e], a0);
            a1 = fmaf(wr[e], cr1[e], a1);
        }
        g_W2[(uint32_t)b * 8192 + (toff(c0 + cl, ch0) >> 2)] =
            pack_h2(a0 * Ss[ch0], a1 * Ss[ch0 + 1]);
    }
}

// =============================================================================
// K4: y = W2_b @ q + b_out via fp16 single-pass mma, LayerNorm over C fused.
// 64 positions per block; smem 50.5 KB.
// =============================================================================
#define K3_W   0
#define K3_Q   32768
#define K3_RS  49152
#define K3_RQ  50176
#define K3_MU  51200
#define K3_RST 51456
#define K3_SMEM 51712

__global__ __launch_bounds__(256, 2)
void k_out(const float* __restrict__ b_out, const float* __restrict__ ln_g,
           const float* __restrict__ ln_b, float* __restrict__ out)
{
    extern __shared__ char smc[];
    const uint32_t sb = smem_u32(smc);
    float* red_s = (float*)(smc + K3_RS);    // [4][64]
    float* red_q = (float*)(smc + K3_RQ);    // [4][64]
    float* mu_s  = (float*)(smc + K3_MU);    // [64]
    float* rs_s  = (float*)(smc + K3_RST);   // [64]

    const int tid = threadIdx.x;
    const int warp = tid >> 5, lane = tid & 31;
    const int wm = warp & 3, wn = warp >> 2;          // wn in {0,1}
    const int b    = blockIdx.x >> 8;
    const int tile = blockIdx.x & 255;
    const int n0   = tile << 6;
    const size_t qt = (size_t)blockIdx.x * 1024;      // uint4 base of q tile

#pragma unroll
    for (int i = 0; i < 8; i++) {
        int lin = tid + i * 256;              // 2048 uint4: W2 tile
        ((uint4*)(smc + K3_W))[lin] = ((const uint4*)g_W2)[(size_t)b * 2048 + lin];
    }
#pragma unroll
    for (int i = 0; i < 4; i++) {
        int lin = tid + i * 256;              // 1024 uint4: q tile
        ((uint4*)(smc + K3_Q))[lin] = ((const uint4*)g_q)[qt + lin];
    }
    __syncthreads();

    const int l7 = lane & 7, lb3 = (lane >> 3) & 1, lb4 = (lane >> 4) & 1;
    float acc[2][4][4];
#pragma unroll
    for (int mt = 0; mt < 2; mt++)
#pragma unroll
        for (int u = 0; u < 4; u++)
#pragma unroll
            for (int r = 0; r < 4; r++) acc[mt][u][r] = 0.f;

    // single fp16 pass
#pragma unroll
    for (int k = 0; k < 8; k++) {
        uint32_t a[2][4];
#pragma unroll
        for (int mt = 0; mt < 2; mt++)
            ldsm4(a[mt], sb + K3_W + toff(wm * 32 + mt * 16 + l7 + lb3 * 8, k * 16 + lb4 * 8));
        uint32_t bfr[2][4];
#pragma unroll
        for (int nt = 0; nt < 2; nt++)
            ldsm4(bfr[nt], sb + K3_Q + toff(wn * 32 + nt * 16 + l7 + lb4 * 8, k * 16 + lb3 * 8));
#pragma unroll
        for (int mt = 0; mt < 2; mt++)
#pragma unroll
            for (int u = 0; u < 4; u++)
                mma16816(acc[mt][u], a[mt], bfr[u >> 1][(u & 1) * 2], bfr[u >> 1][(u & 1) * 2 + 1]);
    }

    // bias
#pragma unroll
    for (int mt = 0; mt < 2; mt++)
#pragma unroll
        for (int h8 = 0; h8 < 2; h8++) {
            const float bo = b_out[wm * 32 + mt * 16 + h8 * 8 + (lane >> 2)];
#pragma unroll
            for (int u = 0; u < 4; u++) {
                acc[mt][u][h8 * 2]     += bo;
                acc[mt][u][h8 * 2 + 1] += bo;
            }
        }

    // LN partials
#pragma unroll
    for (int u = 0; u < 4; u++)
#pragma unroll
        for (int j = 0; j < 2; j++) {
            float a0 = acc[0][u][j],     a1 = acc[0][u][2 + j];
            float a2 = acc[1][u][j],     a3 = acc[1][u][2 + j];
            float s = a0 + a1 + a2 + a3;
            float q = a0 * a0 + a1 * a1 + a2 * a2 + a3 * a3;
            s += __shfl_xor_sync(0xffffffffu, s, 4);
            q += __shfl_xor_sync(0xffffffffu, q, 4);
            s += __shfl_xor_sync(0xffffffffu, s, 8);
            q += __shfl_xor_sync(0xffffffffu, q, 8);
            s += __shfl_xor_sync(0xffffffffu, s, 16);
            q += __shfl_xor_sync(0xffffffffu, q, 16);
            if ((lane >> 2) == 0) {
                int col = wn * 32 + u * 8 + (lane & 3) * 2 + j;
                red_s[wm * 64 + col] = s;
                red_q[wm * 64 + col] = q;
            }
        }
    __syncthreads();

    if (tid < 64) {
        float s = red_s[tid] + red_s[64 + tid] + red_s[128 + tid] + red_s[192 + tid];
        float q = red_q[tid] + red_q[64 + tid] + red_q[128 + tid] + red_q[192 + tid];
        float mu  = s * (1.0f / 128.0f);
        float var = q * (1.0f / 128.0f) - mu * mu;
        mu_s[tid] = mu;
        rs_s[tid] = rsqrtf(var + 1e-5f);
    }
    __syncthreads();

#pragma unroll
    for (int mt = 0; mt < 2; mt++)
#pragma unroll
        for (int h8 = 0; h8 < 2; h8++) {
            const int c = wm * 32 + mt * 16 + h8 * 8 + (lane >> 2);
            const float g  = ln_g[c];
            const float bb = ln_b[c];
            float* rowp = out + ((size_t)b * NCH + c) * NPOS + n0 + wn * 32 + (lane & 3) * 2;
#pragma unroll
            for (int u = 0; u < 4; u++) {
                int col = wn * 32 + u * 8 + (lane & 3) * 2;
                float v0 = (acc[mt][u][h8 * 2]     - mu_s[col])     * rs_s[col]     * g + bb;
                float v1 = (acc[mt][u][h8 * 2 + 1] - mu_s[col + 1]) * rs_s[col + 1] * g + bb;
                *(float2*)(rowp + u * 8) = make_float2(v0, v1);
            }
        }
}

// =============================================================================
extern "C" void kernel_launch(void* const* d_in, const int* in_sizes, int n_in,
                              void* d_out, int out_size)
{
    const float* x     = (const float*)d_in[0];
    const float* w_qkv = (const float*)d_in[1];
    const float* w_out = (const float*)d_in[2];
    const float* b_out = (const float*)d_in[3];
    const float* ln_g  = (const float*)d_in[4];
    const float* ln_b  = (const float*)d_in[5];
    float* out = (float*)d_out;

    cudaFuncSetAttribute(k_qkv, cudaFuncAttributeMaxDynamicSharedMemorySize, Q_SMEM);
    cudaFuncSetAttribute(k_out, cudaFuncAttributeMaxDynamicSharedMemorySize, K3_SMEM);

    k_prep<<<96, 256>>>(w_qkv);
    k_qkv<<<4096, 256, Q_SMEM>>>(x);
    k_red<<<272, 128>>>();
    k_w2<<<128, 256>>>(w_out);
    k_out<<<4096, 256, K3_SMEM>>>(b_out, ln_g, ln_b, out);
}

// round 11
// speedup vs baseline: 2.5667x; 1.0497x over previous
#include <cuda_runtime.h>
#include <cuda_fp16.h>
#include <cuda_bf16.h>
#include <math.h>
#include <stdint.h>

#define NPOS 16384          // H*W
#define NB   16             // batch
#define NCH  128            // C == hidden
#define NTILE (NB * NPOS / 64)   // 4096 64-row tiles

// ---------------- device scratch (allocation-free rule: __device__ globals) ----
__device__ uint32_t g_q   [NTILE * 4096];   // q fp16 pairs, swizzled 64x128 tiles
__device__ uint32_t g_part[NTILE * 2176];   // per tile: 2048 bf16x2 ctx + 128 f32 se
__device__ float    g_ctx [NB * 4224];      // reduced per batch (4096 ctx + 128 se)
__device__ uint32_t g_W2  [NB * 8192];      // fused W2 fp16, swizzled 128x128 per b
__device__ uint32_t g_wsw [3 * 8192];       // w_qkv fp16, 3 swizzled 128x128 chunks

// ---------------- helpers -------------------------------------------------------
__device__ __forceinline__ uint32_t smem_u32(const void* p) {
    uint32_t a;
    asm("{ .reg .u64 t; cvta.to.shared.u64 t, %1; cvt.u32.u64 %0, t; }" : "=r"(a) : "l"(p));
    return a;
}
// swizzled byte offset within a 128-col b16 tile (256B rows)
__device__ __forceinline__ uint32_t toff(int r, int c) {
    return (uint32_t)(r * 256 + (((c >> 3) ^ (r & 7)) << 4) + ((c & 7) << 1));
}
// swizzled byte offset within a 64-col b16 tile (128B rows)
__device__ __forceinline__ uint32_t toff64(int r, int c) {
    return (uint32_t)(r * 128 + (((c >> 3) ^ (r & 7)) << 4) + ((c & 7) << 1));
}
__device__ __forceinline__ void ldsm4(uint32_t* r, uint32_t a) {
    asm volatile("ldmatrix.sync.aligned.m8n8.x4.shared.b16 {%0,%1,%2,%3}, [%4];"
                 : "=r"(r[0]), "=r"(r[1]), "=r"(r[2]), "=r"(r[3]) : "r"(a));
}
__device__ __forceinline__ void ldsm4t(uint32_t* r, uint32_t a) {
    asm volatile("ldmatrix.sync.aligned.m8n8.x4.trans.shared.b16 {%0,%1,%2,%3}, [%4];"
                 : "=r"(r[0]), "=r"(r[1]), "=r"(r[2]), "=r"(r[3]) : "r"(a));
}
__device__ __forceinline__ void mma16816(float* d, const uint32_t* a, uint32_t b0, uint32_t b1) {
    asm volatile(
        "mma.sync.aligned.m16n8k16.row.col.f32.f16.f16.f32 "
        "{%0,%1,%2,%3}, {%4,%5,%6,%7}, {%8,%9}, {%0,%1,%2,%3};"
        : "+f"(d[0]), "+f"(d[1]), "+f"(d[2]), "+f"(d[3])
        : "r"(a[0]), "r"(a[1]), "r"(a[2]), "r"(a[3]), "r"(b0), "r"(b1));
}
__device__ __forceinline__ uint32_t pack_h2(float a, float b) {
    __half2 h = __floats2half2_rn(a, b);
    return *(uint32_t*)&h;
}
__device__ __forceinline__ void split_h(float v0, float v1, uint32_t& hi, uint32_t& lo) {
    __half2 h = __floats2half2_rn(v0, v1);
    float2 hf = __half22float2(h);
    __half2 l = __floats2half2_rn(v0 - hf.x, v1 - hf.y);
    hi = *(uint32_t*)&h;
    lo = *(uint32_t*)&l;
}
__device__ __forceinline__ void cp_async16(uint32_t smem_dst, const void* gsrc) {
    asm volatile("cp.async.cg.shared.global [%0], [%1], 16;" :: "r"(smem_dst), "l"(gsrc));
}

// =============================================================================
// K0: convert w_qkv to fp16, pre-swizzled, 3 chunks of 128x128
// =============================================================================
__global__ __launch_bounds__(256)
void k_prep(const float* __restrict__ w_qkv)
{
    int idx = blockIdx.x * 256 + threadIdx.x;   // 24576 items
    int chunk = idx >> 13, rem = idx & 8191;
    int o = rem >> 6, cp = rem & 63;
    int c0 = cp * 2;
    float v0 = w_qkv[(size_t)(chunk * 128 + o) * NCH + c0];
    float v1 = w_qkv[(size_t)(chunk * 128 + o) * NCH + c0 + 1];
    g_wsw[(uint32_t)chunk * 8192 + (toff(o, c0) >> 2)] = pack_h2(v0, v1);
}

// =============================================================================
// K1: fused qkv-GEMM (fp16 single-pass) + q-softmax + ctx partial (split fp16).
// 64 positions/block, 4096 blocks, 2 CTAs/SM.  cp.async prefetch of next w
// chunk overlapped with the epilogue.
// smem: X 16K (x -> v_hi) | W 32K (w chunk -> ctx red staging) |
//       EKH 16K | EKL 16K | VL 16K | SE 1K  = 97 KB
// =============================================================================
#define Q_X   0
#define Q_W   16384
#define Q_EKH 49152
#define Q_EKL 65536
#define Q_VL  81920
#define Q_SE  98304
#define Q_SMEM 99328

__global__ __launch_bounds__(256, 2)
void k_qkv(const float* __restrict__ x)
{
    extern __shared__ char smc[];
    const uint32_t sb = smem_u32(smc);
    const int tid = threadIdx.x;
    const int warp = tid >> 5, lane = tid & 31;
    const int wm = warp & 1, wn = warp >> 1;        // wm: 2x32 pos, wn: 4x32 ch

    const int b    = blockIdx.x >> 8;
    const int tile = blockIdx.x & 255;
    const int n0   = tile << 6;
    const uint32_t gt = (uint32_t)blockIdx.x;

    // ---- load x tile [c=128][p=64] as fp16, toff64 swizzle; w chunk0 copy ----
    {
        const float* xb = x + (size_t)b * NCH * NPOS + n0;
#pragma unroll
        for (int i = 0; i < 8; i++) {
            int lin = tid + i * 256;            // 2048 float4
            int c = lin >> 4, pq = lin & 15;
            float4 v = *(const float4*)(xb + (size_t)c * NPOS + pq * 4);
            uint32_t o = toff64(c, pq * 4);
            *(uint32_t*)(smc + Q_X + o)     = pack_h2(v.x, v.y);
            *(uint32_t*)(smc + Q_X + o + 4) = pack_h2(v.z, v.w);
        }
#pragma unroll
        for (int i = 0; i < 8; i++) {
            int lin = tid + i * 256;            // 2048 uint4
            ((uint4*)(smc + Q_W))[lin] = ((const uint4*)g_wsw)[lin];
        }
    }
    __syncthreads();

    const int l7 = lane & 7, lb3 = (lane >> 3) & 1, lb4 = (lane >> 4) & 1;
    const float scale = 0.17677669529663687f;   // 32^-0.5

    for (int chunk = 0; chunk < 3; chunk++) {
        float acc[2][4][4];
#pragma unroll
        for (int mt = 0; mt < 2; mt++)
#pragma unroll
            for (int u = 0; u < 4; u++)
#pragma unroll
                for (int r = 0; r < 4; r++) acc[mt][u][r] = 0.f;

        // single fp16 pass
#pragma unroll
        for (int k = 0; k < 8; k++) {
            uint32_t a[2][4];
#pragma unroll
            for (int mt = 0; mt < 2; mt++)
                ldsm4t(a[mt], sb + Q_X + toff64(k * 16 + l7 + lb4 * 8, wm * 32 + mt * 16 + lb3 * 8));
            uint32_t bfr[2][4];
#pragma unroll
            for (int nt = 0; nt < 2; nt++)
                ldsm4(bfr[nt], sb + Q_W + toff(wn * 32 + nt * 16 + l7 + lb4 * 8, k * 16 + lb3 * 8));
#pragma unroll
            for (int mt = 0; mt < 2; mt++)
#pragma unroll
                for (int u = 0; u < 4; u++)
                    mma16816(acc[mt][u], a[mt], bfr[u >> 1][(u & 1) * 2],
                             bfr[u >> 1][(u & 1) * 2 + 1]);
        }
        __syncthreads();   // all MMA reads of Q_W (and Q_X for chunk 2) complete

        // prefetch next w chunk into Q_W, overlapped with the epilogue below
        if (chunk < 2) {
#pragma unroll
            for (int i = 0; i < 8; i++) {
                int lin = tid + i * 256;
                cp_async16(sb + Q_W + lin * 16, ((const uint4*)g_wsw) + (chunk + 1) * 2048 + lin);
            }
            asm volatile("cp.async.commit_group;");
        }

        // ---- epilogues ----
        if (chunk == 0) {
            // q: softmax over 32 channels per head -> global fp16 swizzled tiles
#pragma unroll
            for (int mt = 0; mt < 2; mt++)
#pragma unroll
            for (int h8 = 0; h8 < 2; h8++) {
                float e[4][2];
                float s = 0.f;
#pragma unroll
                for (int u = 0; u < 4; u++)
#pragma unroll
                    for (int j = 0; j < 2; j++) {
                        float v = __expf(acc[mt][u][h8 * 2 + j]);
                        e[u][j] = v;
                        s += v;
                    }
                s += __shfl_xor_sync(0xffffffffu, s, 1);
                s += __shfl_xor_sync(0xffffffffu, s, 2);
                const float inv = scale / s;
                const int p = wm * 32 + mt * 16 + h8 * 8 + (lane >> 2);
#pragma unroll
                for (int u = 0; u < 4; u++) {
                    int ch0 = wn * 32 + u * 8 + (lane & 3) * 2;
                    g_q[gt * 4096 + (toff(p, ch0) >> 2)] = pack_h2(e[u][0] * inv, e[u][1] * inv);
                }
            }
        } else if (chunk == 1) {
            // ek = exp(k): split fp16 into EKH/EKL; sumexp partials (f32 exact)
            float sep[4][2];
#pragma unroll
            for (int u = 0; u < 4; u++) { sep[u][0] = 0.f; sep[u][1] = 0.f; }
#pragma unroll
            for (int mt = 0; mt < 2; mt++)
#pragma unroll
            for (int h8 = 0; h8 < 2; h8++) {
                const int p = wm * 32 + mt * 16 + h8 * 8 + (lane >> 2);
#pragma unroll
                for (int u = 0; u < 4; u++) {
                    float v0 = __expf(acc[mt][u][h8 * 2]);
                    float v1 = __expf(acc[mt][u][h8 * 2 + 1]);
                    sep[u][0] += v0; sep[u][1] += v1;
                    uint32_t hi, lo;
                    split_h(v0, v1, hi, lo);
                    int ch0 = wn * 32 + u * 8 + (lane & 3) * 2;
                    uint32_t o = toff(p, ch0);
                    *(uint32_t*)(smc + Q_EKH + o) = hi;
                    *(uint32_t*)(smc + Q_EKL + o) = lo;
                }
            }
            float* se = (float*)(smc + Q_SE);
#pragma unroll
            for (int u = 0; u < 4; u++)
#pragma unroll
                for (int j = 0; j < 2; j++) {
                    float s = sep[u][j];
                    s += __shfl_xor_sync(0xffffffffu, s, 4);
                    s += __shfl_xor_sync(0xffffffffu, s, 8);
                    s += __shfl_xor_sync(0xffffffffu, s, 16);
                    if ((lane >> 2) == 0)
                        se[warp * 32 + u * 8 + (lane & 3) * 2 + j] = s;
                }
        } else {
            // v: split fp16 -> X (v_hi) + VL (v_lo); x reads finished at barrier
#pragma unroll
            for (int mt = 0; mt < 2; mt++)
#pragma unroll
            for (int h8 = 0; h8 < 2; h8++) {
                const int p = wm * 32 + mt * 16 + h8 * 8 + (lane >> 2);
#pragma unroll
                for (int u = 0; u < 4; u++) {
                    uint32_t hi, lo;
                    split_h(acc[mt][u][h8 * 2], acc[mt][u][h8 * 2 + 1], hi, lo);
                    int ch0 = wn * 32 + u * 8 + (lane & 3) * 2;
                    uint32_t o = toff(p, ch0);
                    *(uint32_t*)(smc + Q_X + o)  = hi;
                    *(uint32_t*)(smc + Q_VL + o) = lo;
                }
            }
        }

        if (chunk < 2) asm volatile("cp.async.wait_group 0;" ::: "memory");
        __syncthreads();
    }

    // ---- ctx partial: ctx_h[d][e] = sum_p ek[p,d] v[p,e]  (3 split passes) ----
    const int h = warp & 3, ks = warp >> 2;
    float ctx[2][4][4];
#pragma unroll
    for (int mt = 0; mt < 2; mt++)
#pragma unroll
        for (int u = 0; u < 4; u++)
#pragma unroll
            for (int r = 0; r < 4; r++) ctx[mt][u][r] = 0.f;

    {
        const int PA[3] = {Q_EKH, Q_EKH, Q_EKL};
        const int PB[3] = {Q_X,   Q_VL,  Q_X};
#pragma unroll
        for (int ps = 0; ps < 3; ps++) {
            const uint32_t aB = sb + PA[ps], bB = sb + PB[ps];
#pragma unroll
            for (int kk = 0; kk < 2; kk++) {
                const int p0 = ks * 32 + kk * 16;
                uint32_t a[2][4];
#pragma unroll
                for (int mt = 0; mt < 2; mt++)
                    ldsm4t(a[mt], aB + toff(p0 + l7 + lb4 * 8, h * 32 + mt * 16 + lb3 * 8));
                uint32_t bfr[2][4];
#pragma unroll
                for (int nt = 0; nt < 2; nt++)
                    ldsm4t(bfr[nt], bB + toff(p0 + l7 + lb3 * 8, h * 32 + nt * 16 + lb4 * 8));
#pragma unroll
                for (int mt = 0; mt < 2; mt++)
#pragma unroll
                    for (int u = 0; u < 4; u++)
                        mma16816(ctx[mt][u], a[mt], bfr[u >> 1][(u & 1) * 2],
                                 bfr[u >> 1][(u & 1) * 2 + 1]);
            }
        }
    }

    // two-phase ctx staging into 16KB red buffer (aliases Q_W)
    float* rb = (float*)(smc + Q_W);
    __syncthreads();
    if (ks == 0) {
#pragma unroll
        for (int mt = 0; mt < 2; mt++)
#pragma unroll
            for (int u = 0; u < 4; u++) {
                int dr = mt * 16 + (lane >> 2), e = u * 8 + (lane & 3) * 2;
                float* r = rb + h * 1024;
                r[dr * 32 + e]           = ctx[mt][u][0];
                r[dr * 32 + e + 1]       = ctx[mt][u][1];
                r[(dr + 8) * 32 + e]     = ctx[mt][u][2];
                r[(dr + 8) * 32 + e + 1] = ctx[mt][u][3];
            }
    }
    __syncthreads();
    if (ks == 1) {
#pragma unroll
        for (int mt = 0; mt < 2; mt++)
#pragma unroll
            for (int u = 0; u < 4; u++) {
                int dr = mt * 16 + (lane >> 2), e = u * 8 + (lane & 3) * 2;
                float* r = rb + h * 1024;
                r[dr * 32 + e]           += ctx[mt][u][0];
                r[dr * 32 + e + 1]       += ctx[mt][u][1];
                r[(dr + 8) * 32 + e]     += ctx[mt][u][2];
                r[(dr + 8) * 32 + e + 1] += ctx[mt][u][3];
            }
    }
    __syncthreads();

    // ---- write block partial: 2048 bf16x2 ctx + 128 f32 se ----
    {
        const size_t pbase = (size_t)gt * 2176;
#pragma unroll
        for (int i = 0; i < 8; i++) {
            int idx = tid + i * 256;            // 2048
            __nv_bfloat162 pkt = __float22bfloat162_rn(make_float2(rb[idx * 2], rb[idx * 2 + 1]));
            g_part[pbase + idx] = *(uint32_t*)&pkt;
        }
        if (tid < 128) {
            const float* se = (const float*)(smc + Q_SE);
            int wq = tid >> 5;
            float s = se[(wq * 2) * 32 + (tid & 31)] + se[(wq * 2 + 1) * 32 + (tid & 31)];
            g_part[pbase + 2048 + tid] = __float_as_uint(s);
        }
    }
}

// =============================================================================
// K2: reduce 256 tile partials per batch -> g_ctx[b][4224]
// =============================================================================
__global__ __launch_bounds__(128, 8)
void k_red()
{
    const int b = blockIdx.x / 17, g = blockIdx.x % 17;
    const int col = g * 128 + threadIdx.x;      // 0..2175
    const uint32_t* src = g_part + (size_t)b * 256 * 2176 + col;
    if (col < 2048) {
        float s0 = 0.f, s1 = 0.f;
#pragma unroll 4
        for (int t = 0; t < 256; t++) {
            uint32_t u = src[(size_t)t * 2176];
            float2 f = __bfloat1622float2(*(__nv_bfloat162*)&u);
            s0 += f.x; s1 += f.y;
        }
        g_ctx[b * 4224 + col * 2]     = s0;
        g_ctx[b * 4224 + col * 2 + 1] = s1;
    } else {
        float s = 0.f;
#pragma unroll 4
        for (int t = 0; t < 256; t++)
            s += __uint_as_float(src[(size_t)t * 2176]);
        g_ctx[b * 4224 + 4096 + (col - 2048)] = s;
    }
}

// =============================================================================
// K3: normalize ctx, build fused W2 (fp16), swizzled tiles per b.
// grid = NB*32 (4 c-rows per block) for latency hiding.
// =============================================================================
__global__ __launch_bounds__(256, 4)
void k_w2(const float* __restrict__ w_out)
{
    __shared__ float ctxs[4224];     // [h][d][33]
    __shared__ float Ss[128];
    __shared__ float ws2[512];       // 4 c-rows x 128 ch

    const int b  = blockIdx.x >> 5;
    const int c0 = (blockIdx.x & 31) * 4;
    const int tid = threadIdx.x;

    for (int lin = tid; lin < 512; lin += 256)
        ws2[lin] = w_out[(size_t)(c0 + (lin >> 7)) * 128 + (lin & 127)];
    for (int idx = tid; idx < 4096; idx += 256) {
        int h = idx >> 10, de = idx & 1023;
        ctxs[h * 1056 + (de >> 5) * 33 + (de & 31)] = g_ctx[b * 4224 + idx];
    }
    if (tid < 128) Ss[tid] = 1.0f / g_ctx[b * 4224 + 4096 + tid];
    __syncthreads();

    {
        int cl = tid >> 6, cpp = tid & 63;       // 256 threads = 4 rows x 64 pairs
        int ch0 = cpp * 2;
        int h = ch0 >> 5, d = ch0 & 31;
        const float* cr0 = &ctxs[h * 1056 + d * 33];
        const float* cr1 = cr0 + 33;
        const float* wr  = &ws2[cl * 128 + h * 32];
        float a0 = 0.f, a1 = 0.f;
#pragma unroll
        for (int e = 0; e < 32; e++) {
            a0 = fmaf(wr[e], cr0[e], a0);
            a1 = fmaf(wr[e], cr1[e], a1);
        }
        g_W2[(uint32_t)b * 8192 + (toff(c0 + cl, ch0) >> 2)] =
            pack_h2(a0 * Ss[ch0], a1 * Ss[ch0 + 1]);
    }
}

// =============================================================================
// K4: y = W2_b @ q + b_out via fp16 mma, LayerNorm fused.  2 q-tiles per block
// (W2 loaded once), grid 2048, 2 CTAs/SM.  smem ~68 KB.
// =============================================================================
#define K3_W   0
#define K3_Q0  32768
#define K3_Q1  49152
#define K3_RS  65536
#define K3_RQ  66560
#define K3_MU  67584
#define K3_RST 67840
#define K3_SMEM 68096

__global__ __launch_bounds__(256, 2)
void k_out(const float* __restrict__ b_out, const float* __restrict__ ln_g,
           const float* __restrict__ ln_b, float* __restrict__ out)
{
    extern __shared__ char smc[];
    const uint32_t sb = smem_u32(smc);
    float* red_s = (float*)(smc + K3_RS);    // [4][64]
    float* red_q = (float*)(smc + K3_RQ);    // [4][64]
    float* mu_s  = (float*)(smc + K3_MU);    // [64]
    float* rs_s  = (float*)(smc + K3_RST);   // [64]

    const int tid = threadIdx.x;
    const int warp = tid >> 5, lane = tid & 31;
    const int wm = warp & 3, wn = warp >> 2;          // wn in {0,1}
    const int b  = blockIdx.x >> 7;
    const int tp = blockIdx.x & 127;                  // tile pair
    const size_t qt0 = ((size_t)b * 256 + tp * 2) * 1024;   // uint4 base, tile 0

#pragma unroll
    for (int i = 0; i < 8; i++) {
        int lin = tid + i * 256;              // 2048 uint4: W2 tile
        ((uint4*)(smc + K3_W))[lin] = ((const uint4*)g_W2)[(size_t)b * 2048 + lin];
    }
#pragma unroll
    for (int i = 0; i < 8; i++) {
        int lin = tid + i * 256;              // 2048 uint4: two q tiles
        ((uint4*)(smc + K3_Q0))[lin] = ((const uint4*)g_q)[qt0 + lin];
    }
    __syncthreads();

    const int l7 = lane & 7, lb3 = (lane >> 3) & 1, lb4 = (lane >> 4) & 1;

    for (int t2 = 0; t2 < 2; t2++) {
        const int n0 = (tp * 2 + t2) << 6;
        const uint32_t qB = sb + K3_Q0 + t2 * 16384;

        float acc[2][4][4];
#pragma unroll
        for (int mt = 0; mt < 2; mt++)
#pragma unroll
            for (int u = 0; u < 4; u++)
#pragma unroll
                for (int r = 0; r < 4; r++) acc[mt][u][r] = 0.f;

#pragma unroll
        for (int k = 0; k < 8; k++) {
            uint32_t a[2][4];
#pragma unroll
            for (int mt = 0; mt < 2; mt++)
                ldsm4(a[mt], sb + K3_W + toff(wm * 32 + mt * 16 + l7 + lb3 * 8, k * 16 + lb4 * 8));
            uint32_t bfr[2][4];
#pragma unroll
            for (int nt = 0; nt < 2; nt++)
                ldsm4(bfr[nt], qB + toff(wn * 32 + nt * 16 + l7 + lb4 * 8, k * 16 + lb3 * 8));
#pragma unroll
            for (int mt = 0; mt < 2; mt++)
#pragma unroll
                for (int u = 0; u < 4; u++)
                    mma16816(acc[mt][u], a[mt], bfr[u >> 1][(u & 1) * 2], bfr[u >> 1][(u & 1) * 2 + 1]);
        }

        // bias
#pragma unroll
        for (int mt = 0; mt < 2; mt++)
#pragma unroll
            for (int h8 = 0; h8 < 2; h8++) {
                const float bo = b_out[wm * 32 + mt * 16 + h8 * 8 + (lane >> 2)];
#pragma unroll
                for (int u = 0; u < 4; u++) {
                    acc[mt][u][h8 * 2]     += bo;
                    acc[mt][u][h8 * 2 + 1] += bo;
                }
            }

        // LN partials
#pragma unroll
        for (int u = 0; u < 4; u++)
#pragma unroll
            for (int j = 0; j < 2; j++) {
                float a0 = acc[0][u][j],     a1 = acc[0][u][2 + j];
                float a2 = acc[1][u][j],     a3 = acc[1][u][2 + j];
                float s = a0 + a1 + a2 + a3;
                float q = a0 * a0 + a1 * a1 + a2 * a2 + a3 * a3;
                s += __shfl_xor_sync(0xffffffffu, s, 4);
                q += __shfl_xor_sync(0xffffffffu, q, 4);
                s += __shfl_xor_sync(0xffffffffu, s, 8);
                q += __shfl_xor_sync(0xffffffffu, q, 8);
                s += __shfl_xor_sync(0xffffffffu, s, 16);
                q += __shfl_xor_sync(0xffffffffu, q, 16);
                if ((lane >> 2) == 0) {
                    int col = wn * 32 + u * 8 + (lane & 3) * 2 + j;
                    red_s[wm * 64 + col] = s;
                    red_q[wm * 64 + col] = q;
                }
            }
        __syncthreads();

        if (tid < 64) {
            float s = red_s[tid] + red_s[64 + tid] + red_s[128 + tid] + red_s[192 + tid];
            float q = red_q[tid] + red_q[64 + tid] + red_q[128 + tid] + red_q[192 + tid];
            float mu  = s * (1.0f / 128.0f);
            float var = q * (1.0f / 128.0f) - mu * mu;
            mu_s[tid] = mu;
            rs_s[tid] = rsqrtf(var + 1e-5f);
        }
        __syncthreads();

#pragma unroll
        for (int mt = 0; mt < 2; mt++)
#pragma unroll
            for (int h8 = 0; h8 < 2; h8++) {
                const int c = wm * 32 + mt * 16 + h8 * 8 + (lane >> 2);
                const float g  = ln_g[c];
                const float bb = ln_b[c];
                float* rowp = out + ((size_t)b * NCH + c) * NPOS + n0 + wn * 32 + (lane & 3) * 2;
#pragma unroll
                for (int u = 0; u < 4; u++) {
                    int col = wn * 32 + u * 8 + (lane & 3) * 2;
                    float v0 = (acc[mt][u][h8 * 2]     - mu_s[col])     * rs_s[col]     * g + bb;
                    float v1 = (acc[mt][u][h8 * 2 + 1] - mu_s[col + 1]) * rs_s[col + 1] * g + bb;
                    *(float2*)(rowp + u * 8) = make_float2(v0, v1);
                }
            }
        __syncthreads();   // red/mu buffers reused by next tile
    }
}

// =============================================================================
extern "C" void kernel_launch(void* const* d_in, const int* in_sizes, int n_in,
                              void* d_out, int out_size)
{
    const float* x     = (const float*)d_in[0];
    const float* w_qkv = (const float*)d_in[1];
    const float* w_out = (const float*)d_in[2];
    const float* b_out = (const float*)d_in[3];
    const float* ln_g  = (const float*)d_in[4];
    const float* ln_b  = (const float*)d_in[5];
    float* out = (float*)d_out;

    cudaFuncSetAttribute(k_qkv, cudaFuncAttributeMaxDynamicSharedMemorySize, Q_SMEM);
    cudaFuncSetAttribute(k_out, cudaFuncAttributeMaxDynamicSharedMemorySize, K3_SMEM);

    k_prep<<<96, 256>>>(w_qkv);
    k_qkv<<<4096, 256, Q_SMEM>>>(x);
    k_red<<<272, 128>>>();
    k_w2<<<512, 256>>>(w_out);
    k_out<<<2048, 256, K3_SMEM>>>(b_out, ln_g, ln_b, out);
}